// round 10
// baseline (speedup 1.0000x reference)
#include <cuda_runtime.h>
#include <math.h>
#include <cuda_bf16.h>

// Problem constants
#define S_  1536
#define N_  1537          // S + 1 (anchor row 0)
#define D_  512
#define H_  4
#define R_  32
#define HR_ 128           // H*R
#define W_  128
#define K_  130           // W + 2
#define HFF_ 1024
#define L_  4

// -------------------- device scratch (no allocations allowed) --------------------
__device__ float g_valA[N_ * D_];
__device__ float g_valB[N_ * D_];
__device__ float g_x[N_ * D_];       // ln2(valB), FFN GEMM1 input
__device__ float g_h[N_ * HFF_];     // FFN hidden
__device__ float g_qk[N_ * 256];     // [n][0:128]=q(h*R+r), [128:256]=k
__device__ float g_stA[N_];
__device__ float g_stB[N_];
__device__ float g_wqk[L_ * D_ * 256]; // transposed wq|wk per layer: [(l*D+d)*256 + c]

// -------------------- helpers --------------------
__device__ __forceinline__ float gelu_exact(float x) {
    return 0.5f * x * (1.0f + erff(x * 0.7071067811865475f));
}

// block reductions for 128-thread blocks (4 warps)
__device__ __forceinline__ float blkSum128(float v, volatile float* red) {
    #pragma unroll
    for (int o = 16; o > 0; o >>= 1) v += __shfl_xor_sync(0xffffffffu, v, o);
    __syncthreads();
    if ((threadIdx.x & 31) == 0) red[threadIdx.x >> 5] = v;
    __syncthreads();
    return red[0] + red[1] + red[2] + red[3];
}
__device__ __forceinline__ float blkMax128(float v, volatile float* red) {
    #pragma unroll
    for (int o = 16; o > 0; o >>= 1) v = fmaxf(v, __shfl_xor_sync(0xffffffffu, v, o));
    __syncthreads();
    if ((threadIdx.x & 31) == 0) red[threadIdx.x >> 5] = v;
    __syncthreads();
    return fmaxf(fmaxf(red[0], red[1]), fmaxf(red[2], red[3]));
}

// -------------------- kernel: transpose wq/wk into GEMM-friendly layout --------------------
// out[(l*D + d)*256 + c]: c<128 -> wq[l, h=c/32, d, r=c%32]; c>=128 -> wk[...]
__global__ void prep_wqk_kernel(const float* __restrict__ wq, const float* __restrict__ wk,
                                float* __restrict__ out) {
    int i = blockIdx.x * blockDim.x + threadIdx.x;      // 0 .. 2^19-1
    int c = i & 255;
    int d = (i >> 8) & 511;
    int l = i >> 17;
    const float* w = (c < 128) ? wq : wk;
    int cc = c & 127;
    int h  = cc >> 5;
    int r  = cc & 31;
    out[i] = w[(((l * H_ + h) * D_ + d) * R_) + r];
}

// -------------------- kernel: embedding + input LN + state init --------------------
__global__ void embed_ln_kernel(const int* __restrict__ ids, const float* __restrict__ emb,
                                const float* __restrict__ pos, const float* __restrict__ g,
                                const float* __restrict__ b, const float* __restrict__ av,
                                const float* __restrict__ ast, const float* __restrict__ sw,
                                const float* __restrict__ sb, float* __restrict__ val,
                                float* __restrict__ st) {
    __shared__ float red[4];
    int n = blockIdx.x, tid = threadIdx.x;   // 128 threads, float4 per thread
    float4* val4 = (float4*)val;
    if (n == 0) {
        val4[tid] = ((const float4*)av)[tid];   // anchor row: raw anchor_val (no LN)
        if (tid == 0) st[0] = ast[0];
        return;
    }
    int t = n - 1;
    int id = ids[t];
    float4 e4 = ((const float4*)(emb + (size_t)id * D_))[tid];
    float4 p4 = ((const float4*)(pos + (size_t)t  * D_))[tid];
    float x0 = e4.x + p4.x, x1 = e4.y + p4.y, x2 = e4.z + p4.z, x3 = e4.w + p4.w;
    float s  = blkSum128(x0 + x1 + x2 + x3, red);
    float sq = blkSum128(x0*x0 + x1*x1 + x2*x2 + x3*x3, red);
    float mean = s * (1.0f / D_);
    float var  = sq * (1.0f / D_) - mean * mean;
    float rstd = rsqrtf(var + 1e-5f);
    float4 g4 = ((const float4*)g)[tid], b4 = ((const float4*)b)[tid];
    float4 y;
    y.x = (x0 - mean) * rstd * g4.x + b4.x;
    y.y = (x1 - mean) * rstd * g4.y + b4.y;
    y.z = (x2 - mean) * rstd * g4.z + b4.z;
    y.w = (x3 - mean) * rstd * g4.w + b4.w;
    val4[(size_t)n * 128 + tid] = y;
    float4 w4 = ((const float4*)sw)[tid];
    float dot = blkSum128(y.x*w4.x + y.y*w4.y + y.z*w4.z + y.w*w4.w, red);
    if (tid == 0) st[n] = dot + sb[0];
}

// -------------------- kernel: generic sgemm, C(MxN) = A(MxK) @ B(KxN) --------------------
// EPI 0: plain; 1: gelu(AB + bias); 2: AB + bias + Cres
#define BM 64
#define BN 64
#define BK 16
template <int EPI>
__global__ void sgemm_kernel(const float* __restrict__ A, const float* __restrict__ B,
                             float* __restrict__ C, const float* __restrict__ bias,
                             const float* __restrict__ Cres, int M, int Nn, int Kk) {
    __shared__ float As[BK][BM];
    __shared__ float Bs[BK][BN];
    int tid = threadIdx.x;
    int bm = blockIdx.x * BM, bn = blockIdx.y * BN;
    int arow = tid >> 2;            // 0..63
    int acol = (tid & 3) << 2;      // 0,4,8,12
    int brow = tid >> 4;            // 0..15
    int bcol = (tid & 15) << 2;     // 0..60
    int tx = tid & 15, ty = tid >> 4;

    float acc[4][4] = {};
    for (int k0 = 0; k0 < Kk; k0 += BK) {
        float4 av;
        if (bm + arow < M)
            av = *(const float4*)(A + (size_t)(bm + arow) * Kk + k0 + acol);
        else
            av = make_float4(0.f, 0.f, 0.f, 0.f);
        As[acol + 0][arow] = av.x;
        As[acol + 1][arow] = av.y;
        As[acol + 2][arow] = av.z;
        As[acol + 3][arow] = av.w;
        *(float4*)(&Bs[brow][bcol]) =
            *(const float4*)(B + (size_t)(k0 + brow) * Nn + bn + bcol);
        __syncthreads();
        #pragma unroll
        for (int kk = 0; kk < BK; kk++) {
            float4 a4 = *(const float4*)(&As[kk][ty * 4]);
            float4 b4 = *(const float4*)(&Bs[kk][tx * 4]);
            float ar[4] = {a4.x, a4.y, a4.z, a4.w};
            float br[4] = {b4.x, b4.y, b4.z, b4.w};
            #pragma unroll
            for (int i = 0; i < 4; i++)
                #pragma unroll
                for (int j = 0; j < 4; j++)
                    acc[i][j] = fmaf(ar[i], br[j], acc[i][j]);
        }
        __syncthreads();
    }
    int colb = bn + tx * 4;
    float4 bv4 = make_float4(0.f, 0.f, 0.f, 0.f);
    if (EPI != 0) bv4 = *(const float4*)(bias + colb);
    #pragma unroll
    for (int i = 0; i < 4; i++) {
        int row = bm + ty * 4 + i;
        if (row >= M) continue;
        float4 o;
        o.x = acc[i][0]; o.y = acc[i][1]; o.z = acc[i][2]; o.w = acc[i][3];
        if (EPI == 1) {
            o.x = gelu_exact(o.x + bv4.x);
            o.y = gelu_exact(o.y + bv4.y);
            o.z = gelu_exact(o.z + bv4.z);
            o.w = gelu_exact(o.w + bv4.w);
        } else if (EPI == 2) {
            float4 r4 = *(const float4*)(Cres + (size_t)row * Nn + colb);
            o.x += bv4.x + r4.x;
            o.y += bv4.y + r4.y;
            o.z += bv4.z + r4.z;
            o.w += bv4.w + r4.w;
        }
        *(float4*)(C + (size_t)row * Nn + colb) = o;
    }
}

// -------------------- kernel: attention + residual + LN + LN2 (fused) --------------------
// per token n (block), 128 threads (4 warps)
__global__ void attn_kernel(const float* __restrict__ val, const float* __restrict__ st_in,
                            const float* __restrict__ qk, float* __restrict__ val_out,
                            float* __restrict__ x_out, float* __restrict__ st_out,
                            const float* __restrict__ gate_arr, int l,
                            const float* __restrict__ lng, const float* __restrict__ lnb,
                            const float* __restrict__ ln2g, const float* __restrict__ ln2b) {
    __shared__ float s_q[128];
    __shared__ float s_a[K_];
    __shared__ int   s_j[K_];    // -1 encodes invalid
    __shared__ float s_e[K_];
    __shared__ float red[4];

    int n = blockIdx.x;
    int tid = threadIdx.x;
    int lane = tid & 31, wid = tid >> 5;
    float gate = gate_arr[l];

    s_q[tid] = qk[(size_t)n * 256 + tid];
    __syncthreads();

    const float scale = 0.17677669529663687f; // 1/sqrt(32)

    // ---- phase 1: per-neighbor head scores, head softmax, aggregate a ----
    for (int kk = wid; kk < K_; kk += 4) {
        int j; bool valid;
        if (kk == 0) { j = 0; valid = (n > W_); }
        else { int raw = n - (W_ + 1) + kk; valid = (raw >= 0); j = raw > 0 ? raw : 0; }
        const float* krow = qk + (size_t)j * 256 + 128;
        float p0 = s_q[lane]      * __ldg(krow + lane);
        float p1 = s_q[32 + lane] * __ldg(krow + 32 + lane);
        float p2 = s_q[64 + lane] * __ldg(krow + 64 + lane);
        float p3 = s_q[96 + lane] * __ldg(krow + 96 + lane);
        #pragma unroll
        for (int o = 16; o > 0; o >>= 1) {
            p0 += __shfl_xor_sync(0xffffffffu, p0, o);
            p1 += __shfl_xor_sync(0xffffffffu, p1, o);
            p2 += __shfl_xor_sync(0xffffffffu, p2, o);
            p3 += __shfl_xor_sync(0xffffffffu, p3, o);
        }
        if (lane == 0) {
            float s0 = p0 * scale, s1 = p1 * scale, s2 = p2 * scale, s3 = p3 * scale;
            float a0 = fabsf(s0), a1 = fabsf(s1), a2 = fabsf(s2), a3 = fabsf(s3);
            float m = fmaxf(fmaxf(a0, a1), fmaxf(a2, a3));
            float e0 = __expf(a0 - m), e1 = __expf(a1 - m), e2 = __expf(a2 - m), e3 = __expf(a3 - m);
            float den = e0 + e1 + e2 + e3;
            s_a[kk] = (s0 * e0 + s1 * e1 + s2 * e2 + s3 * e3) / den;
            s_j[kk] = valid ? j : -1;
        }
    }
    __syncthreads();

    // ---- phase 2: signed softmax over neighbors, times gathered state ----
    float a0v = s_a[tid]; int j0 = s_j[tid];
    float ab0 = (j0 >= 0) ? fabsf(a0v) : -1e30f;
    float a1v = 0.f; int j1 = -1; float ab1 = -1e30f;
    if (tid < K_ - 128) { a1v = s_a[128 + tid]; j1 = s_j[128 + tid]; ab1 = (j1 >= 0) ? fabsf(a1v) : -1e30f; }
    float mx = blkMax128(fmaxf(ab0, ab1), red);
    float e0 = (j0 >= 0) ? __expf(ab0 - mx) : 0.f;
    float e1 = (j1 >= 0) ? __expf(ab1 - mx) : 0.f;
    float inv = 1.0f / blkSum128(e0 + e1, red);

    float ds = 0.f;
    {
        float sg0 = (a0v > 0.f) ? 1.f : ((a0v < 0.f) ? -1.f : 0.f);
        float ee0 = (j0 >= 0) ? e0 * inv * sg0 * __ldg(st_in + j0) : 0.f;
        s_e[tid] = ee0; ds += ee0;
        if (tid < K_ - 128) {
            float sg1 = (a1v > 0.f) ? 1.f : ((a1v < 0.f) ? -1.f : 0.f);
            float ee1 = (j1 >= 0) ? e1 * inv * sg1 * __ldg(st_in + j1) : 0.f;
            s_e[128 + tid] = ee1; ds += ee1;
        }
    }
    float d_state = blkSum128(ds, red);  // internal syncthreads also publishes s_e

    // ---- phase 3: d_val gather, residual, LN, LN2 ----
    const float4* val4 = (const float4*)val;
    float4 acc = make_float4(0.f, 0.f, 0.f, 0.f);
    for (int kk = 0; kk < K_; kk++) {
        float e = s_e[kk];
        if (e != 0.f) {
            int j = s_j[kk];
            float4 v = __ldg(&val4[(size_t)j * 128 + tid]);
            acc.x = fmaf(e, v.x, acc.x);
            acc.y = fmaf(e, v.y, acc.y);
            acc.z = fmaf(e, v.z, acc.z);
            acc.w = fmaf(e, v.w, acc.w);
        }
    }
    float4 cur = val4[(size_t)n * 128 + tid];
    float x0 = cur.x + gate * acc.x;
    float x1 = cur.y + gate * acc.y;
    float x2 = cur.z + gate * acc.z;
    float x3 = cur.w + gate * acc.w;

    float s  = blkSum128(x0 + x1 + x2 + x3, red);
    float sq = blkSum128(x0*x0 + x1*x1 + x2*x2 + x3*x3, red);
    float mean = s * (1.0f / D_);
    float var  = sq * (1.0f / D_) - mean * mean;
    float rstd = rsqrtf(var + 1e-5f);
    float4 g4 = ((const float4*)lng)[tid], b4 = ((const float4*)lnb)[tid];
    float y0 = (x0 - mean) * rstd * g4.x + b4.x;
    float y1 = (x1 - mean) * rstd * g4.y + b4.y;
    float y2 = (x2 - mean) * rstd * g4.z + b4.z;
    float y3 = (x3 - mean) * rstd * g4.w + b4.w;
    ((float4*)val_out)[(size_t)n * 128 + tid] = make_float4(y0, y1, y2, y3);

    // second LN (ln2) fused -> FFN input
    float s2  = blkSum128(y0 + y1 + y2 + y3, red);
    float sq2 = blkSum128(y0*y0 + y1*y1 + y2*y2 + y3*y3, red);
    float mean2 = s2 * (1.0f / D_);
    float var2  = sq2 * (1.0f / D_) - mean2 * mean2;
    float rstd2 = rsqrtf(var2 + 1e-5f);
    float4 g24 = ((const float4*)ln2g)[tid], b24 = ((const float4*)ln2b)[tid];
    float4 xo;
    xo.x = (y0 - mean2) * rstd2 * g24.x + b24.x;
    xo.y = (y1 - mean2) * rstd2 * g24.y + b24.y;
    xo.z = (y2 - mean2) * rstd2 * g24.z + b24.z;
    xo.w = (y3 - mean2) * rstd2 * g24.w + b24.w;
    ((float4*)x_out)[(size_t)n * 128 + tid] = xo;

    if (tid == 0) st_out[n] = st_in[n] + gate * d_state;
}

// -------------------- launch --------------------
extern "C" void kernel_launch(void* const* d_in, const int* in_sizes, int n_in,
                              void* d_out, int out_size) {
    const int*   ids     = (const int*)d_in[0];
    const float* embed   = (const float*)d_in[1];
    const float* pos     = (const float*)d_in[2];
    const float* ln_in_g = (const float*)d_in[3];
    const float* ln_in_b = (const float*)d_in[4];
    const float* anc_st  = (const float*)d_in[5];
    const float* anc_val = (const float*)d_in[6];
    const float* state_w = (const float*)d_in[7];
    const float* state_b = (const float*)d_in[8];
    const float* wq      = (const float*)d_in[9];
    const float* wk      = (const float*)d_in[10];
    const float* gate    = (const float*)d_in[11];
    const float* ln_g    = (const float*)d_in[12];
    const float* ln_b    = (const float*)d_in[13];
    const float* ffn_w1  = (const float*)d_in[14];
    const float* ffn_b1  = (const float*)d_in[15];
    const float* ffn_w2  = (const float*)d_in[16];
    const float* ffn_b2  = (const float*)d_in[17];
    const float* ln2_g   = (const float*)d_in[18];
    const float* ln2_b   = (const float*)d_in[19];
    float* out = (float*)d_out;

    float *valA, *valB, *x, *h, *qk, *stA, *stB, *wqk;
    cudaGetSymbolAddress((void**)&valA, g_valA);
    cudaGetSymbolAddress((void**)&valB, g_valB);
    cudaGetSymbolAddress((void**)&x,    g_x);
    cudaGetSymbolAddress((void**)&h,    g_h);
    cudaGetSymbolAddress((void**)&qk,   g_qk);
    cudaGetSymbolAddress((void**)&stA,  g_stA);
    cudaGetSymbolAddress((void**)&stB,  g_stB);
    cudaGetSymbolAddress((void**)&wqk,  g_wqk);

    prep_wqk_kernel<<<(L_ * D_ * 256) / 256, 256>>>(wq, wk, wqk);
    embed_ln_kernel<<<N_, 128>>>(ids, embed, pos, ln_in_g, ln_in_b, anc_val, anc_st,
                                 state_w, state_b, valA, stA);

    float* s_in = stA;
    float* s_out = stB;
    const int MB = (N_ + BM - 1) / BM;   // 25
    for (int l = 0; l < L_; l++) {
        dim3 gqk(MB, 256 / BN);
        sgemm_kernel<0><<<gqk, 256>>>(valA, wqk + (size_t)l * D_ * 256, qk,
                                      nullptr, nullptr, N_, 256, D_);
        attn_kernel<<<N_, 128>>>(valA, s_in, qk, valB, x, s_out, gate, l,
                                 ln_g + l * D_, ln_b + l * D_,
                                 ln2_g + l * D_, ln2_b + l * D_);
        dim3 g1(MB, HFF_ / BN);
        sgemm_kernel<1><<<g1, 256>>>(x, ffn_w1 + (size_t)l * D_ * HFF_, h,
                                     ffn_b1 + l * HFF_, nullptr, N_, HFF_, D_);
        float* dst = (l == L_ - 1) ? out : valA;
        dim3 g2(MB, D_ / BN);
        sgemm_kernel<2><<<g2, 256>>>(h, ffn_w2 + (size_t)l * HFF_ * D_, dst,
                                     ffn_b2 + l * D_, valB, N_, D_, HFF_);
        float* t = s_in; s_in = s_out; s_out = t;
    }
}

// round 11
// speedup vs baseline: 1.0031x; 1.0031x over previous
#include <cuda_runtime.h>
#include <math.h>
#include <cuda_bf16.h>

// Problem constants
#define S_  1536
#define N_  1537          // S + 1 (anchor row 0)
#define D_  512
#define H_  4
#define R_  32
#define HR_ 128           // H*R
#define W_  128
#define K_  130           // W + 2
#define HFF_ 1024
#define L_  4

// -------------------- device scratch (no allocations allowed) --------------------
__device__ float g_valA[N_ * D_];
__device__ float g_valB[N_ * D_];
__device__ float g_x[N_ * D_];       // ln2(valB), FFN GEMM1 input
__device__ float g_h[N_ * HFF_];     // FFN hidden
__device__ float g_qk[N_ * 256];     // [n][0:128]=q(h*R+r), [128:256]=k
__device__ float g_stA[N_];
__device__ float g_stB[N_];
__device__ float g_wqk[L_ * D_ * 256]; // transposed wq|wk per layer: [(l*D+d)*256 + c]

// -------------------- helpers --------------------
__device__ __forceinline__ float gelu_exact(float x) {
    return 0.5f * x * (1.0f + erff(x * 0.7071067811865475f));
}

// block reductions for 128-thread blocks (4 warps)
__device__ __forceinline__ float blkSum128(float v, volatile float* red) {
    #pragma unroll
    for (int o = 16; o > 0; o >>= 1) v += __shfl_xor_sync(0xffffffffu, v, o);
    __syncthreads();
    if ((threadIdx.x & 31) == 0) red[threadIdx.x >> 5] = v;
    __syncthreads();
    return red[0] + red[1] + red[2] + red[3];
}
__device__ __forceinline__ float blkMax128(float v, volatile float* red) {
    #pragma unroll
    for (int o = 16; o > 0; o >>= 1) v = fmaxf(v, __shfl_xor_sync(0xffffffffu, v, o));
    __syncthreads();
    if ((threadIdx.x & 31) == 0) red[threadIdx.x >> 5] = v;
    __syncthreads();
    return fmaxf(fmaxf(red[0], red[1]), fmaxf(red[2], red[3]));
}

// -------------------- kernel: transpose wq/wk into GEMM-friendly layout --------------------
// out[(l*D + d)*256 + c]: c<128 -> wq[l, h=c/32, d, r=c%32]; c>=128 -> wk[...]
__global__ void prep_wqk_kernel(const float* __restrict__ wq, const float* __restrict__ wk,
                                float* __restrict__ out) {
    int i = blockIdx.x * blockDim.x + threadIdx.x;      // 0 .. 2^19-1
    int c = i & 255;
    int d = (i >> 8) & 511;
    int l = i >> 17;
    const float* w = (c < 128) ? wq : wk;
    int cc = c & 127;
    int h  = cc >> 5;
    int r  = cc & 31;
    out[i] = w[(((l * H_ + h) * D_ + d) * R_) + r];
}

// -------------------- kernel: embedding + input LN + state init --------------------
__global__ void embed_ln_kernel(const int* __restrict__ ids, const float* __restrict__ emb,
                                const float* __restrict__ pos, const float* __restrict__ g,
                                const float* __restrict__ b, const float* __restrict__ av,
                                const float* __restrict__ ast, const float* __restrict__ sw,
                                const float* __restrict__ sb, float* __restrict__ val,
                                float* __restrict__ st) {
    __shared__ float red[4];
    int n = blockIdx.x, tid = threadIdx.x;   // 128 threads, float4 per thread
    float4* val4 = (float4*)val;
    if (n == 0) {
        val4[tid] = ((const float4*)av)[tid];   // anchor row: raw anchor_val (no LN)
        if (tid == 0) st[0] = ast[0];
        return;
    }
    int t = n - 1;
    int id = ids[t];
    float4 e4 = ((const float4*)(emb + (size_t)id * D_))[tid];
    float4 p4 = ((const float4*)(pos + (size_t)t  * D_))[tid];
    float x0 = e4.x + p4.x, x1 = e4.y + p4.y, x2 = e4.z + p4.z, x3 = e4.w + p4.w;
    float s  = blkSum128(x0 + x1 + x2 + x3, red);
    float sq = blkSum128(x0*x0 + x1*x1 + x2*x2 + x3*x3, red);
    float mean = s * (1.0f / D_);
    float var  = sq * (1.0f / D_) - mean * mean;
    float rstd = rsqrtf(var + 1e-5f);
    float4 g4 = ((const float4*)g)[tid], b4 = ((const float4*)b)[tid];
    float4 y;
    y.x = (x0 - mean) * rstd * g4.x + b4.x;
    y.y = (x1 - mean) * rstd * g4.y + b4.y;
    y.z = (x2 - mean) * rstd * g4.z + b4.z;
    y.w = (x3 - mean) * rstd * g4.w + b4.w;
    val4[(size_t)n * 128 + tid] = y;
    float4 w4 = ((const float4*)sw)[tid];
    float dot = blkSum128(y.x*w4.x + y.y*w4.y + y.z*w4.z + y.w*w4.w, red);
    if (tid == 0) st[n] = dot + sb[0];
}

// -------------------- kernel: generic sgemm, C(MxN) = A(MxK) @ B(KxN) --------------------
// EPI 0: plain; 1: gelu(AB + bias); 2: AB + bias + Cres
#define BM 64
#define BN 64
#define BK 16
template <int EPI>
__global__ void sgemm_kernel(const float* __restrict__ A, const float* __restrict__ B,
                             float* __restrict__ C, const float* __restrict__ bias,
                             const float* __restrict__ Cres, int M, int Nn, int Kk) {
    __shared__ float As[BK][BM];
    __shared__ float Bs[BK][BN];
    int tid = threadIdx.x;
    int bm = blockIdx.x * BM, bn = blockIdx.y * BN;
    int arow = tid >> 2;            // 0..63
    int acol = (tid & 3) << 2;      // 0,4,8,12
    int brow = tid >> 4;            // 0..15
    int bcol = (tid & 15) << 2;     // 0..60
    int tx = tid & 15, ty = tid >> 4;

    float acc[4][4] = {};
    for (int k0 = 0; k0 < Kk; k0 += BK) {
        float4 av;
        if (bm + arow < M)
            av = *(const float4*)(A + (size_t)(bm + arow) * Kk + k0 + acol);
        else
            av = make_float4(0.f, 0.f, 0.f, 0.f);
        As[acol + 0][arow] = av.x;
        As[acol + 1][arow] = av.y;
        As[acol + 2][arow] = av.z;
        As[acol + 3][arow] = av.w;
        *(float4*)(&Bs[brow][bcol]) =
            *(const float4*)(B + (size_t)(k0 + brow) * Nn + bn + bcol);
        __syncthreads();
        #pragma unroll
        for (int kk = 0; kk < BK; kk++) {
            float4 a4 = *(const float4*)(&As[kk][ty * 4]);
            float4 b4 = *(const float4*)(&Bs[kk][tx * 4]);
            float ar[4] = {a4.x, a4.y, a4.z, a4.w};
            float br[4] = {b4.x, b4.y, b4.z, b4.w};
            #pragma unroll
            for (int i = 0; i < 4; i++)
                #pragma unroll
                for (int j = 0; j < 4; j++)
                    acc[i][j] = fmaf(ar[i], br[j], acc[i][j]);
        }
        __syncthreads();
    }
    int colb = bn + tx * 4;
    float4 bv4 = make_float4(0.f, 0.f, 0.f, 0.f);
    if (EPI != 0) bv4 = *(const float4*)(bias + colb);
    #pragma unroll
    for (int i = 0; i < 4; i++) {
        int row = bm + ty * 4 + i;
        if (row >= M) continue;
        float4 o;
        o.x = acc[i][0]; o.y = acc[i][1]; o.z = acc[i][2]; o.w = acc[i][3];
        if (EPI == 1) {
            o.x = gelu_exact(o.x + bv4.x);
            o.y = gelu_exact(o.y + bv4.y);
            o.z = gelu_exact(o.z + bv4.z);
            o.w = gelu_exact(o.w + bv4.w);
        } else if (EPI == 2) {
            float4 r4 = *(const float4*)(Cres + (size_t)row * Nn + colb);
            o.x += bv4.x + r4.x;
            o.y += bv4.y + r4.y;
            o.z += bv4.z + r4.z;
            o.w += bv4.w + r4.w;
        }
        *(float4*)(C + (size_t)row * Nn + colb) = o;
    }
}

// -------------------- kernel: attention + residual + LN + LN2 (fused) --------------------
// per token n (block), 128 threads (4 warps)
__global__ void attn_kernel(const float* __restrict__ val, const float* __restrict__ st_in,
                            const float* __restrict__ qk, float* __restrict__ val_out,
                            float* __restrict__ x_out, float* __restrict__ st_out,
                            const float* __restrict__ gate_arr, int l,
                            const float* __restrict__ lng, const float* __restrict__ lnb,
                            const float* __restrict__ ln2g, const float* __restrict__ ln2b) {
    __shared__ float s_q[128];
    __shared__ float s_a[K_];
    __shared__ int   s_j[K_];    // -1 encodes invalid
    __shared__ float s_e[K_];
    __shared__ float red[4];

    int n = blockIdx.x;
    int tid = threadIdx.x;
    int lane = tid & 31, wid = tid >> 5;
    float gate = gate_arr[l];

    s_q[tid] = qk[(size_t)n * 256 + tid];
    __syncthreads();

    const float scale = 0.17677669529663687f; // 1/sqrt(32)

    // ---- phase 1: per-neighbor head scores, head softmax, aggregate a ----
    for (int kk = wid; kk < K_; kk += 4) {
        int j; bool valid;
        if (kk == 0) { j = 0; valid = (n > W_); }
        else { int raw = n - (W_ + 1) + kk; valid = (raw >= 0); j = raw > 0 ? raw : 0; }
        const float* krow = qk + (size_t)j * 256 + 128;
        float p0 = s_q[lane]      * __ldg(krow + lane);
        float p1 = s_q[32 + lane] * __ldg(krow + 32 + lane);
        float p2 = s_q[64 + lane] * __ldg(krow + 64 + lane);
        float p3 = s_q[96 + lane] * __ldg(krow + 96 + lane);
        #pragma unroll
        for (int o = 16; o > 0; o >>= 1) {
            p0 += __shfl_xor_sync(0xffffffffu, p0, o);
            p1 += __shfl_xor_sync(0xffffffffu, p1, o);
            p2 += __shfl_xor_sync(0xffffffffu, p2, o);
            p3 += __shfl_xor_sync(0xffffffffu, p3, o);
        }
        if (lane == 0) {
            float s0 = p0 * scale, s1 = p1 * scale, s2 = p2 * scale, s3 = p3 * scale;
            float a0 = fabsf(s0), a1 = fabsf(s1), a2 = fabsf(s2), a3 = fabsf(s3);
            float m = fmaxf(fmaxf(a0, a1), fmaxf(a2, a3));
            float e0 = __expf(a0 - m), e1 = __expf(a1 - m), e2 = __expf(a2 - m), e3 = __expf(a3 - m);
            float den = e0 + e1 + e2 + e3;
            s_a[kk] = (s0 * e0 + s1 * e1 + s2 * e2 + s3 * e3) / den;
            s_j[kk] = valid ? j : -1;
        }
    }
    __syncthreads();

    // ---- phase 2: signed softmax over neighbors, times gathered state ----
    float a0v = s_a[tid]; int j0 = s_j[tid];
    float ab0 = (j0 >= 0) ? fabsf(a0v) : -1e30f;
    float a1v = 0.f; int j1 = -1; float ab1 = -1e30f;
    if (tid < K_ - 128) { a1v = s_a[128 + tid]; j1 = s_j[128 + tid]; ab1 = (j1 >= 0) ? fabsf(a1v) : -1e30f; }
    float mx = blkMax128(fmaxf(ab0, ab1), red);
    float e0 = (j0 >= 0) ? __expf(ab0 - mx) : 0.f;
    float e1 = (j1 >= 0) ? __expf(ab1 - mx) : 0.f;
    float inv = 1.0f / blkSum128(e0 + e1, red);

    float ds = 0.f;
    {
        float sg0 = (a0v > 0.f) ? 1.f : ((a0v < 0.f) ? -1.f : 0.f);
        float ee0 = (j0 >= 0) ? e0 * inv * sg0 * __ldg(st_in + j0) : 0.f;
        s_e[tid] = ee0; ds += ee0;
        if (tid < K_ - 128) {
            float sg1 = (a1v > 0.f) ? 1.f : ((a1v < 0.f) ? -1.f : 0.f);
            float ee1 = (j1 >= 0) ? e1 * inv * sg1 * __ldg(st_in + j1) : 0.f;
            s_e[128 + tid] = ee1; ds += ee1;
        }
    }
    float d_state = blkSum128(ds, red);  // internal syncthreads also publishes s_e

    // ---- phase 3: d_val gather, residual, LN, LN2 ----
    const float4* val4 = (const float4*)val;
    float4 acc = make_float4(0.f, 0.f, 0.f, 0.f);
    for (int kk = 0; kk < K_; kk++) {
        float e = s_e[kk];
        if (e != 0.f) {
            int j = s_j[kk];
            float4 v = __ldg(&val4[(size_t)j * 128 + tid]);
            acc.x = fmaf(e, v.x, acc.x);
            acc.y = fmaf(e, v.y, acc.y);
            acc.z = fmaf(e, v.z, acc.z);
            acc.w = fmaf(e, v.w, acc.w);
        }
    }
    float4 cur = val4[(size_t)n * 128 + tid];
    float x0 = cur.x + gate * acc.x;
    float x1 = cur.y + gate * acc.y;
    float x2 = cur.z + gate * acc.z;
    float x3 = cur.w + gate * acc.w;

    float s  = blkSum128(x0 + x1 + x2 + x3, red);
    float sq = blkSum128(x0*x0 + x1*x1 + x2*x2 + x3*x3, red);
    float mean = s * (1.0f / D_);
    float var  = sq * (1.0f / D_) - mean * mean;
    float rstd = rsqrtf(var + 1e-5f);
    float4 g4 = ((const float4*)lng)[tid], b4 = ((const float4*)lnb)[tid];
    float y0 = (x0 - mean) * rstd * g4.x + b4.x;
    float y1 = (x1 - mean) * rstd * g4.y + b4.y;
    float y2 = (x2 - mean) * rstd * g4.z + b4.z;
    float y3 = (x3 - mean) * rstd * g4.w + b4.w;
    ((float4*)val_out)[(size_t)n * 128 + tid] = make_float4(y0, y1, y2, y3);

    // second LN (ln2) fused -> FFN input
    float s2  = blkSum128(y0 + y1 + y2 + y3, red);
    float sq2 = blkSum128(y0*y0 + y1*y1 + y2*y2 + y3*y3, red);
    float mean2 = s2 * (1.0f / D_);
    float var2  = sq2 * (1.0f / D_) - mean2 * mean2;
    float rstd2 = rsqrtf(var2 + 1e-5f);
    float4 g24 = ((const float4*)ln2g)[tid], b24 = ((const float4*)ln2b)[tid];
    float4 xo;
    xo.x = (y0 - mean2) * rstd2 * g24.x + b24.x;
    xo.y = (y1 - mean2) * rstd2 * g24.y + b24.y;
    xo.z = (y2 - mean2) * rstd2 * g24.z + b24.z;
    xo.w = (y3 - mean2) * rstd2 * g24.w + b24.w;
    ((float4*)x_out)[(size_t)n * 128 + tid] = xo;

    if (tid == 0) st_out[n] = st_in[n] + gate * d_state;
}

// -------------------- launch --------------------
extern "C" void kernel_launch(void* const* d_in, const int* in_sizes, int n_in,
                              void* d_out, int out_size) {
    const int*   ids     = (const int*)d_in[0];
    const float* embed   = (const float*)d_in[1];
    const float* pos     = (const float*)d_in[2];
    const float* ln_in_g = (const float*)d_in[3];
    const float* ln_in_b = (const float*)d_in[4];
    const float* anc_st  = (const float*)d_in[5];
    const float* anc_val = (const float*)d_in[6];
    const float* state_w = (const float*)d_in[7];
    const float* state_b = (const float*)d_in[8];
    const float* wq      = (const float*)d_in[9];
    const float* wk      = (const float*)d_in[10];
    const float* gate    = (const float*)d_in[11];
    const float* ln_g    = (const float*)d_in[12];
    const float* ln_b    = (const float*)d_in[13];
    const float* ffn_w1  = (const float*)d_in[14];
    const float* ffn_b1  = (const float*)d_in[15];
    const float* ffn_w2  = (const float*)d_in[16];
    const float* ffn_b2  = (const float*)d_in[17];
    const float* ln2_g   = (const float*)d_in[18];
    const float* ln2_b   = (const float*)d_in[19];
    float* out = (float*)d_out;

    float *valA, *valB, *x, *h, *qk, *stA, *stB, *wqk;
    cudaGetSymbolAddress((void**)&valA, g_valA);
    cudaGetSymbolAddress((void**)&valB, g_valB);
    cudaGetSymbolAddress((void**)&x,    g_x);
    cudaGetSymbolAddress((void**)&h,    g_h);
    cudaGetSymbolAddress((void**)&qk,   g_qk);
    cudaGetSymbolAddress((void**)&stA,  g_stA);
    cudaGetSymbolAddress((void**)&stB,  g_stB);
    cudaGetSymbolAddress((void**)&wqk,  g_wqk);

    prep_wqk_kernel<<<(L_ * D_ * 256) / 256, 256>>>(wq, wk, wqk);
    embed_ln_kernel<<<N_, 128>>>(ids, embed, pos, ln_in_g, ln_in_b, anc_val, anc_st,
                                 state_w, state_b, valA, stA);

    float* s_in = stA;
    float* s_out = stB;
    const int MB = (N_ + BM - 1) / BM;   // 25
    for (int l = 0; l < L_; l++) {
        dim3 gqk(MB, 256 / BN);
        sgemm_kernel<0><<<gqk, 256>>>(valA, wqk + (size_t)l * D_ * 256, qk,
                                      nullptr, nullptr, N_, 256, D_);
        attn_kernel<<<N_, 128>>>(valA, s_in, qk, valB, x, s_out, gate, l,
                                 ln_g + l * D_, ln_b + l * D_,
                                 ln2_g + l * D_, ln2_b + l * D_);
        dim3 g1(MB, HFF_ / BN);
        sgemm_kernel<1><<<g1, 256>>>(x, ffn_w1 + (size_t)l * D_ * HFF_, h,
                                     ffn_b1 + l * HFF_, nullptr, N_, HFF_, D_);
        float* dst = (l == L_ - 1) ? out : valA;
        dim3 g2(MB, D_ / BN);
        sgemm_kernel<2><<<g2, 256>>>(h, ffn_w2 + (size_t)l * HFF_ * D_, dst,
                                     ffn_b2 + l * D_, valB, N_, D_, HFF_);
        float* t = s_in; s_in = s_out; s_out = t;
    }
}

// round 13
// speedup vs baseline: 1.0045x; 1.0014x over previous
#include <cuda_runtime.h>
#include <math.h>
#include <cuda_bf16.h>

// Problem constants
#define S_  1536
#define N_  1537          // S + 1 (anchor row 0)
#define D_  512
#define H_  4
#define R_  32
#define HR_ 128           // H*R
#define W_  128
#define K_  130           // W + 2
#define HFF_ 1024
#define L_  4

// -------------------- device scratch (no allocations allowed) --------------------
__device__ float g_valA[N_ * D_];
__device__ float g_valB[N_ * D_];
__device__ float g_x[N_ * D_];       // ln2(valB), FFN GEMM1 input
__device__ float g_h[N_ * HFF_];     // FFN hidden
__device__ float g_qk[N_ * 256];     // [n][0:128]=q(h*R+r), [128:256]=k
__device__ float g_stA[N_];
__device__ float g_stB[N_];
__device__ float g_wqk[L_ * D_ * 256]; // transposed wq|wk per layer: [(l*D+d)*256 + c]

// -------------------- helpers --------------------
__device__ __forceinline__ float gelu_exact(float x) {
    return 0.5f * x * (1.0f + erff(x * 0.7071067811865475f));
}

// block reductions for 128-thread blocks (4 warps)
__device__ __forceinline__ float blkSum128(float v, volatile float* red) {
    #pragma unroll
    for (int o = 16; o > 0; o >>= 1) v += __shfl_xor_sync(0xffffffffu, v, o);
    __syncthreads();
    if ((threadIdx.x & 31) == 0) red[threadIdx.x >> 5] = v;
    __syncthreads();
    return red[0] + red[1] + red[2] + red[3];
}
__device__ __forceinline__ float blkMax128(float v, volatile float* red) {
    #pragma unroll
    for (int o = 16; o > 0; o >>= 1) v = fmaxf(v, __shfl_xor_sync(0xffffffffu, v, o));
    __syncthreads();
    if ((threadIdx.x & 31) == 0) red[threadIdx.x >> 5] = v;
    __syncthreads();
    return fmaxf(fmaxf(red[0], red[1]), fmaxf(red[2], red[3]));
}

// -------------------- kernel: transpose wq/wk into GEMM-friendly layout --------------------
// out[(l*D + d)*256 + c]: c<128 -> wq[l, h=c/32, d, r=c%32]; c>=128 -> wk[...]
__global__ void prep_wqk_kernel(const float* __restrict__ wq, const float* __restrict__ wk,
                                float* __restrict__ out) {
    int i = blockIdx.x * blockDim.x + threadIdx.x;      // 0 .. 2^19-1
    int c = i & 255;
    int d = (i >> 8) & 511;
    int l = i >> 17;
    const float* w = (c < 128) ? wq : wk;
    int cc = c & 127;
    int h  = cc >> 5;
    int r  = cc & 31;
    out[i] = w[(((l * H_ + h) * D_ + d) * R_) + r];
}

// -------------------- kernel: embedding + input LN + state init --------------------
__global__ void embed_ln_kernel(const int* __restrict__ ids, const float* __restrict__ emb,
                                const float* __restrict__ pos, const float* __restrict__ g,
                                const float* __restrict__ b, const float* __restrict__ av,
                                const float* __restrict__ ast, const float* __restrict__ sw,
                                const float* __restrict__ sb, float* __restrict__ val,
                                float* __restrict__ st) {
    __shared__ float red[4];
    int n = blockIdx.x, tid = threadIdx.x;   // 128 threads, float4 per thread
    float4* val4 = (float4*)val;
    if (n == 0) {
        val4[tid] = ((const float4*)av)[tid];   // anchor row: raw anchor_val (no LN)
        if (tid == 0) st[0] = ast[0];
        return;
    }
    int t = n - 1;
    int id = ids[t];
    float4 e4 = ((const float4*)(emb + (size_t)id * D_))[tid];
    float4 p4 = ((const float4*)(pos + (size_t)t  * D_))[tid];
    float x0 = e4.x + p4.x, x1 = e4.y + p4.y, x2 = e4.z + p4.z, x3 = e4.w + p4.w;
    float s  = blkSum128(x0 + x1 + x2 + x3, red);
    float sq = blkSum128(x0*x0 + x1*x1 + x2*x2 + x3*x3, red);
    float mean = s * (1.0f / D_);
    float var  = sq * (1.0f / D_) - mean * mean;
    float rstd = rsqrtf(var + 1e-5f);
    float4 g4 = ((const float4*)g)[tid], b4 = ((const float4*)b)[tid];
    float4 y;
    y.x = (x0 - mean) * rstd * g4.x + b4.x;
    y.y = (x1 - mean) * rstd * g4.y + b4.y;
    y.z = (x2 - mean) * rstd * g4.z + b4.z;
    y.w = (x3 - mean) * rstd * g4.w + b4.w;
    val4[(size_t)n * 128 + tid] = y;
    float4 w4 = ((const float4*)sw)[tid];
    float dot = blkSum128(y.x*w4.x + y.y*w4.y + y.z*w4.z + y.w*w4.w, red);
    if (tid == 0) st[n] = dot + sb[0];
}

// -------------------- kernel: generic sgemm, C(MxN) = A(MxK) @ B(KxN) --------------------
// EPI 0: plain; 1: gelu(AB + bias); 2: AB + bias + Cres
#define BM 64
#define BN 64
#define BK 16
template <int EPI>
__global__ void sgemm_kernel(const float* __restrict__ A, const float* __restrict__ B,
                             float* __restrict__ C, const float* __restrict__ bias,
                             const float* __restrict__ Cres, int M, int Nn, int Kk) {
    __shared__ float As[BK][BM];
    __shared__ float Bs[BK][BN];
    int tid = threadIdx.x;
    int bm = blockIdx.x * BM, bn = blockIdx.y * BN;
    int arow = tid >> 2;            // 0..63
    int acol = (tid & 3) << 2;      // 0,4,8,12
    int brow = tid >> 4;            // 0..15
    int bcol = (tid & 15) << 2;     // 0..60
    int tx = tid & 15, ty = tid >> 4;

    float acc[4][4] = {};
    for (int k0 = 0; k0 < Kk; k0 += BK) {
        float4 av;
        if (bm + arow < M)
            av = *(const float4*)(A + (size_t)(bm + arow) * Kk + k0 + acol);
        else
            av = make_float4(0.f, 0.f, 0.f, 0.f);
        As[acol + 0][arow] = av.x;
        As[acol + 1][arow] = av.y;
        As[acol + 2][arow] = av.z;
        As[acol + 3][arow] = av.w;
        *(float4*)(&Bs[brow][bcol]) =
            *(const float4*)(B + (size_t)(k0 + brow) * Nn + bn + bcol);
        __syncthreads();
        #pragma unroll
        for (int kk = 0; kk < BK; kk++) {
            float4 a4 = *(const float4*)(&As[kk][ty * 4]);
            float4 b4 = *(const float4*)(&Bs[kk][tx * 4]);
            float ar[4] = {a4.x, a4.y, a4.z, a4.w};
            float br[4] = {b4.x, b4.y, b4.z, b4.w};
            #pragma unroll
            for (int i = 0; i < 4; i++)
                #pragma unroll
                for (int j = 0; j < 4; j++)
                    acc[i][j] = fmaf(ar[i], br[j], acc[i][j]);
        }
        __syncthreads();
    }
    int colb = bn + tx * 4;
    float4 bv4 = make_float4(0.f, 0.f, 0.f, 0.f);
    if (EPI != 0) bv4 = *(const float4*)(bias + colb);
    #pragma unroll
    for (int i = 0; i < 4; i++) {
        int row = bm + ty * 4 + i;
        if (row >= M) continue;
        float4 o;
        o.x = acc[i][0]; o.y = acc[i][1]; o.z = acc[i][2]; o.w = acc[i][3];
        if (EPI == 1) {
            o.x = gelu_exact(o.x + bv4.x);
            o.y = gelu_exact(o.y + bv4.y);
            o.z = gelu_exact(o.z + bv4.z);
            o.w = gelu_exact(o.w + bv4.w);
        } else if (EPI == 2) {
            float4 r4 = *(const float4*)(Cres + (size_t)row * Nn + colb);
            o.x += bv4.x + r4.x;
            o.y += bv4.y + r4.y;
            o.z += bv4.z + r4.z;
            o.w += bv4.w + r4.w;
        }
        *(float4*)(C + (size_t)row * Nn + colb) = o;
    }
}

// -------------------- kernel: attention + residual + LN + LN2 (fused) --------------------
// per token n (block), 128 threads (4 warps)
__global__ void attn_kernel(const float* __restrict__ val, const float* __restrict__ st_in,
                            const float* __restrict__ qk, float* __restrict__ val_out,
                            float* __restrict__ x_out, float* __restrict__ st_out,
                            const float* __restrict__ gate_arr, int l,
                            const float* __restrict__ lng, const float* __restrict__ lnb,
                            const float* __restrict__ ln2g, const float* __restrict__ ln2b) {
    __shared__ float s_q[128];
    __shared__ float s_a[K_];
    __shared__ int   s_j[K_];    // -1 encodes invalid
    __shared__ float s_e[K_];
    __shared__ float red[4];

    int n = blockIdx.x;
    int tid = threadIdx.x;
    int lane = tid & 31, wid = tid >> 5;
    float gate = gate_arr[l];

    s_q[tid] = qk[(size_t)n * 256 + tid];
    __syncthreads();

    const float scale = 0.17677669529663687f; // 1/sqrt(32)

    // ---- phase 1: per-neighbor head scores, head softmax, aggregate a ----
    for (int kk = wid; kk < K_; kk += 4) {
        int j; bool valid;
        if (kk == 0) { j = 0; valid = (n > W_); }
        else { int raw = n - (W_ + 1) + kk; valid = (raw >= 0); j = raw > 0 ? raw : 0; }
        const float* krow = qk + (size_t)j * 256 + 128;
        float p0 = s_q[lane]      * __ldg(krow + lane);
        float p1 = s_q[32 + lane] * __ldg(krow + 32 + lane);
        float p2 = s_q[64 + lane] * __ldg(krow + 64 + lane);
        float p3 = s_q[96 + lane] * __ldg(krow + 96 + lane);
        #pragma unroll
        for (int o = 16; o > 0; o >>= 1) {
            p0 += __shfl_xor_sync(0xffffffffu, p0, o);
            p1 += __shfl_xor_sync(0xffffffffu, p1, o);
            p2 += __shfl_xor_sync(0xffffffffu, p2, o);
            p3 += __shfl_xor_sync(0xffffffffu, p3, o);
        }
        if (lane == 0) {
            float s0 = p0 * scale, s1 = p1 * scale, s2 = p2 * scale, s3 = p3 * scale;
            float a0 = fabsf(s0), a1 = fabsf(s1), a2 = fabsf(s2), a3 = fabsf(s3);
            float m = fmaxf(fmaxf(a0, a1), fmaxf(a2, a3));
            float e0 = __expf(a0 - m), e1 = __expf(a1 - m), e2 = __expf(a2 - m), e3 = __expf(a3 - m);
            float den = e0 + e1 + e2 + e3;
            s_a[kk] = (s0 * e0 + s1 * e1 + s2 * e2 + s3 * e3) / den;
            s_j[kk] = valid ? j : -1;
        }
    }
    __syncthreads();

    // ---- phase 2: signed softmax over neighbors, times gathered state ----
    float a0v = s_a[tid]; int j0 = s_j[tid];
    float ab0 = (j0 >= 0) ? fabsf(a0v) : -1e30f;
    float a1v = 0.f; int j1 = -1; float ab1 = -1e30f;
    if (tid < K_ - 128) { a1v = s_a[128 + tid]; j1 = s_j[128 + tid]; ab1 = (j1 >= 0) ? fabsf(a1v) : -1e30f; }
    float mx = blkMax128(fmaxf(ab0, ab1), red);
    float e0 = (j0 >= 0) ? __expf(ab0 - mx) : 0.f;
    float e1 = (j1 >= 0) ? __expf(ab1 - mx) : 0.f;
    float inv = 1.0f / blkSum128(e0 + e1, red);

    float ds = 0.f;
    {
        float sg0 = (a0v > 0.f) ? 1.f : ((a0v < 0.f) ? -1.f : 0.f);
        float ee0 = (j0 >= 0) ? e0 * inv * sg0 * __ldg(st_in + j0) : 0.f;
        s_e[tid] = ee0; ds += ee0;
        if (tid < K_ - 128) {
            float sg1 = (a1v > 0.f) ? 1.f : ((a1v < 0.f) ? -1.f : 0.f);
            float ee1 = (j1 >= 0) ? e1 * inv * sg1 * __ldg(st_in + j1) : 0.f;
            s_e[128 + tid] = ee1; ds += ee1;
        }
    }
    float d_state = blkSum128(ds, red);  // internal syncthreads also publishes s_e

    // ---- phase 3: d_val gather, residual, LN, LN2 ----
    const float4* val4 = (const float4*)val;
    float4 acc = make_float4(0.f, 0.f, 0.f, 0.f);
    for (int kk = 0; kk < K_; kk++) {
        float e = s_e[kk];
        if (e != 0.f) {
            int j = s_j[kk];
            float4 v = __ldg(&val4[(size_t)j * 128 + tid]);
            acc.x = fmaf(e, v.x, acc.x);
            acc.y = fmaf(e, v.y, acc.y);
            acc.z = fmaf(e, v.z, acc.z);
            acc.w = fmaf(e, v.w, acc.w);
        }
    }
    float4 cur = val4[(size_t)n * 128 + tid];
    float x0 = cur.x + gate * acc.x;
    float x1 = cur.y + gate * acc.y;
    float x2 = cur.z + gate * acc.z;
    float x3 = cur.w + gate * acc.w;

    float s  = blkSum128(x0 + x1 + x2 + x3, red);
    float sq = blkSum128(x0*x0 + x1*x1 + x2*x2 + x3*x3, red);
    float mean = s * (1.0f / D_);
    float var  = sq * (1.0f / D_) - mean * mean;
    float rstd = rsqrtf(var + 1e-5f);
    float4 g4 = ((const float4*)lng)[tid], b4 = ((const float4*)lnb)[tid];
    float y0 = (x0 - mean) * rstd * g4.x + b4.x;
    float y1 = (x1 - mean) * rstd * g4.y + b4.y;
    float y2 = (x2 - mean) * rstd * g4.z + b4.z;
    float y3 = (x3 - mean) * rstd * g4.w + b4.w;
    ((float4*)val_out)[(size_t)n * 128 + tid] = make_float4(y0, y1, y2, y3);

    // second LN (ln2) fused -> FFN input
    float s2  = blkSum128(y0 + y1 + y2 + y3, red);
    float sq2 = blkSum128(y0*y0 + y1*y1 + y2*y2 + y3*y3, red);
    float mean2 = s2 * (1.0f / D_);
    float var2  = sq2 * (1.0f / D_) - mean2 * mean2;
    float rstd2 = rsqrtf(var2 + 1e-5f);
    float4 g24 = ((const float4*)ln2g)[tid], b24 = ((const float4*)ln2b)[tid];
    float4 xo;
    xo.x = (y0 - mean2) * rstd2 * g24.x + b24.x;
    xo.y = (y1 - mean2) * rstd2 * g24.y + b24.y;
    xo.z = (y2 - mean2) * rstd2 * g24.z + b24.z;
    xo.w = (y3 - mean2) * rstd2 * g24.w + b24.w;
    ((float4*)x_out)[(size_t)n * 128 + tid] = xo;

    if (tid == 0) st_out[n] = st_in[n] + gate * d_state;
}

// -------------------- launch --------------------
extern "C" void kernel_launch(void* const* d_in, const int* in_sizes, int n_in,
                              void* d_out, int out_size) {
    const int*   ids     = (const int*)d_in[0];
    const float* embed   = (const float*)d_in[1];
    const float* pos     = (const float*)d_in[2];
    const float* ln_in_g = (const float*)d_in[3];
    const float* ln_in_b = (const float*)d_in[4];
    const float* anc_st  = (const float*)d_in[5];
    const float* anc_val = (const float*)d_in[6];
    const float* state_w = (const float*)d_in[7];
    const float* state_b = (const float*)d_in[8];
    const float* wq      = (const float*)d_in[9];
    const float* wk      = (const float*)d_in[10];
    const float* gate    = (const float*)d_in[11];
    const float* ln_g    = (const float*)d_in[12];
    const float* ln_b    = (const float*)d_in[13];
    const float* ffn_w1  = (const float*)d_in[14];
    const float* ffn_b1  = (const float*)d_in[15];
    const float* ffn_w2  = (const float*)d_in[16];
    const float* ffn_b2  = (const float*)d_in[17];
    const float* ln2_g   = (const float*)d_in[18];
    const float* ln2_b   = (const float*)d_in[19];
    float* out = (float*)d_out;

    float *valA, *valB, *x, *h, *qk, *stA, *stB, *wqk;
    cudaGetSymbolAddress((void**)&valA, g_valA);
    cudaGetSymbolAddress((void**)&valB, g_valB);
    cudaGetSymbolAddress((void**)&x,    g_x);
    cudaGetSymbolAddress((void**)&h,    g_h);
    cudaGetSymbolAddress((void**)&qk,   g_qk);
    cudaGetSymbolAddress((void**)&stA,  g_stA);
    cudaGetSymbolAddress((void**)&stB,  g_stB);
    cudaGetSymbolAddress((void**)&wqk,  g_wqk);

    prep_wqk_kernel<<<(L_ * D_ * 256) / 256, 256>>>(wq, wk, wqk);
    embed_ln_kernel<<<N_, 128>>>(ids, embed, pos, ln_in_g, ln_in_b, anc_val, anc_st,
                                 state_w, state_b, valA, stA);

    float* s_in = stA;
    float* s_out = stB;
    const int MB = (N_ + BM - 1) / BM;   // 25
    for (int l = 0; l < L_; l++) {
        dim3 gqk(MB, 256 / BN);
        sgemm_kernel<0><<<gqk, 256>>>(valA, wqk + (size_t)l * D_ * 256, qk,
                                      nullptr, nullptr, N_, 256, D_);
        attn_kernel<<<N_, 128>>>(valA, s_in, qk, valB, x, s_out, gate, l,
                                 ln_g + l * D_, ln_b + l * D_,
                                 ln2_g + l * D_, ln2_b + l * D_);
        dim3 g1(MB, HFF_ / BN);
        sgemm_kernel<1><<<g1, 256>>>(x, ffn_w1 + (size_t)l * D_ * HFF_, h,
                                     ffn_b1 + l * HFF_, nullptr, N_, HFF_, D_);
        float* dst = (l == L_ - 1) ? out : valA;
        dim3 g2(MB, D_ / BN);
        sgemm_kernel<2><<<g2, 256>>>(h, ffn_w2 + (size_t)l * HFF_ * D_, dst,
                                     ffn_b2 + l * D_, valB, N_, D_, HFF_);
        float* t = s_in; s_in = s_out; s_out = t;
    }
}

// round 14
// speedup vs baseline: 1.4390x; 1.4326x over previous
#include <cuda_runtime.h>
#include <math.h>
#include <cuda_bf16.h>

// Problem constants
#define S_  1536
#define N_  1537          // S + 1 (anchor row 0)
#define D_  512
#define H_  4
#define R_  32
#define HR_ 128           // H*R
#define W_  128
#define K_  130           // W + 2
#define HFF_ 1024
#define L_  4

// -------------------- device scratch (no allocations allowed) --------------------
__device__ float g_valA[N_ * D_];
__device__ float g_valB[N_ * D_];
__device__ float g_x[N_ * D_];       // ln2(valB), FFN GEMM1 input
__device__ float g_h[N_ * HFF_];     // FFN hidden
__device__ float g_qk[N_ * 256];     // [n][0:128]=q(h*R+r), [128:256]=k
__device__ float g_stA[N_];
__device__ float g_stB[N_];
__device__ float g_wqk[L_ * D_ * 256]; // transposed wq|wk per layer: [(l*D+d)*256 + c]

// -------------------- helpers --------------------
__device__ __forceinline__ float gelu_exact(float x) {
    return 0.5f * x * (1.0f + erff(x * 0.7071067811865475f));
}

__device__ __forceinline__ unsigned f2tf32(float f) {
    unsigned u;
    asm("cvt.rna.tf32.f32 %0, %1;" : "=r"(u) : "f"(f));
    return u;
}

__device__ __forceinline__ void mma_tf32(float* c, const unsigned* a, unsigned b0, unsigned b1) {
    asm volatile(
        "mma.sync.aligned.m16n8k8.row.col.f32.tf32.tf32.f32 "
        "{%0,%1,%2,%3}, {%4,%5,%6,%7}, {%8,%9}, {%0,%1,%2,%3};\n"
        : "+f"(c[0]), "+f"(c[1]), "+f"(c[2]), "+f"(c[3])
        : "r"(a[0]), "r"(a[1]), "r"(a[2]), "r"(a[3]), "r"(b0), "r"(b1));
}

// block reductions for 128-thread blocks (4 warps)
__device__ __forceinline__ float blkSum128(float v, volatile float* red) {
    #pragma unroll
    for (int o = 16; o > 0; o >>= 1) v += __shfl_xor_sync(0xffffffffu, v, o);
    __syncthreads();
    if ((threadIdx.x & 31) == 0) red[threadIdx.x >> 5] = v;
    __syncthreads();
    return red[0] + red[1] + red[2] + red[3];
}
__device__ __forceinline__ float blkMax128(float v, volatile float* red) {
    #pragma unroll
    for (int o = 16; o > 0; o >>= 1) v = fmaxf(v, __shfl_xor_sync(0xffffffffu, v, o));
    __syncthreads();
    if ((threadIdx.x & 31) == 0) red[threadIdx.x >> 5] = v;
    __syncthreads();
    return fmaxf(fmaxf(red[0], red[1]), fmaxf(red[2], red[3]));
}

// -------------------- kernel: transpose wq/wk into GEMM-friendly layout --------------------
__global__ void prep_wqk_kernel(const float* __restrict__ wq, const float* __restrict__ wk,
                                float* __restrict__ out) {
    int i = blockIdx.x * blockDim.x + threadIdx.x;      // 0 .. 2^19-1
    int c = i & 255;
    int d = (i >> 8) & 511;
    int l = i >> 17;
    const float* w = (c < 128) ? wq : wk;
    int cc = c & 127;
    int h  = cc >> 5;
    int r  = cc & 31;
    out[i] = w[(((l * H_ + h) * D_ + d) * R_) + r];
}

// -------------------- kernel: embedding + input LN + state init --------------------
__global__ void embed_ln_kernel(const int* __restrict__ ids, const float* __restrict__ emb,
                                const float* __restrict__ pos, const float* __restrict__ g,
                                const float* __restrict__ b, const float* __restrict__ av,
                                const float* __restrict__ ast, const float* __restrict__ sw,
                                const float* __restrict__ sb, float* __restrict__ val,
                                float* __restrict__ st) {
    __shared__ float red[4];
    int n = blockIdx.x, tid = threadIdx.x;   // 128 threads, float4 per thread
    float4* val4 = (float4*)val;
    if (n == 0) {
        val4[tid] = ((const float4*)av)[tid];   // anchor row: raw anchor_val (no LN)
        if (tid == 0) st[0] = ast[0];
        return;
    }
    int t = n - 1;
    int id = ids[t];
    float4 e4 = ((const float4*)(emb + (size_t)id * D_))[tid];
    float4 p4 = ((const float4*)(pos + (size_t)t  * D_))[tid];
    float x0 = e4.x + p4.x, x1 = e4.y + p4.y, x2 = e4.z + p4.z, x3 = e4.w + p4.w;
    float s  = blkSum128(x0 + x1 + x2 + x3, red);
    float sq = blkSum128(x0*x0 + x1*x1 + x2*x2 + x3*x3, red);
    float mean = s * (1.0f / D_);
    float var  = sq * (1.0f / D_) - mean * mean;
    float rstd = rsqrtf(var + 1e-5f);
    float4 g4 = ((const float4*)g)[tid], b4 = ((const float4*)b)[tid];
    float4 y;
    y.x = (x0 - mean) * rstd * g4.x + b4.x;
    y.y = (x1 - mean) * rstd * g4.y + b4.y;
    y.z = (x2 - mean) * rstd * g4.z + b4.z;
    y.w = (x3 - mean) * rstd * g4.w + b4.w;
    val4[(size_t)n * 128 + tid] = y;
    float4 w4 = ((const float4*)sw)[tid];
    float dot = blkSum128(y.x*w4.x + y.y*w4.y + y.z*w4.z + y.w*w4.w, red);
    if (tid == 0) st[n] = dot + sb[0];
}

// -------------------- kernel: tf32 tensor-core GEMM --------------------
// C(MxN) = A(MxK) @ B(KxN); A,B row-major fp32 (converted to tf32 in smem).
// Block tile 64x64x32, 128 threads (4 warps, 2x2 warp grid, 32x32 warp tile).
// EPI 0: plain; 1: gelu(AB + bias); 2: AB + bias + Cres
#define GBM 64
#define GBN 64
#define GBK 32
#define ASP 36   // padded A row stride (k-dim 32 + 4)
#define BSP 72   // padded B row stride (n-dim 64 + 8)

template <int EPI>
__global__ __launch_bounds__(128) void mma_gemm_kernel(
        const float* __restrict__ A, const float* __restrict__ B,
        float* __restrict__ C, const float* __restrict__ bias,
        const float* __restrict__ Cres, int M, int Nn, int Kk) {
    __shared__ unsigned As[GBM * ASP];   // As[row][k]
    __shared__ unsigned Bs[GBK * BSP];   // Bs[k][n]

    int tid  = threadIdx.x;
    int lane = tid & 31;
    int wid  = tid >> 5;          // 0..3
    int wm   = wid & 1;           // warp row (2)
    int wn   = wid >> 1;          // warp col (2)
    int g    = lane >> 2;         // groupID 0..7
    int tig  = lane & 3;          // thread-in-group 0..3

    int bm = blockIdx.x * GBM;
    int bn = blockIdx.y * GBN;

    float acc[2][4][4];
    #pragma unroll
    for (int i = 0; i < 2; i++)
        #pragma unroll
        for (int j = 0; j < 4; j++)
            #pragma unroll
            for (int c = 0; c < 4; c++) acc[i][j][c] = 0.f;

    const int KT = Kk / GBK;
    for (int kt = 0; kt < KT; kt++) {
        int k0 = kt * GBK;
        // ---- load A tile: 64 rows x 32 k = 512 float4, 4 per thread ----
        #pragma unroll
        for (int i = 0; i < 4; i++) {
            int idx = tid + i * 128;
            int row = idx >> 3;          // 0..63
            int seg = idx & 7;           // 0..7 (k/4)
            float4 v = make_float4(0.f, 0.f, 0.f, 0.f);
            if (bm + row < M)
                v = *(const float4*)(A + (size_t)(bm + row) * Kk + k0 + seg * 4);
            uint4 u;
            u.x = f2tf32(v.x); u.y = f2tf32(v.y); u.z = f2tf32(v.z); u.w = f2tf32(v.w);
            *(uint4*)(&As[row * ASP + seg * 4]) = u;
        }
        // ---- load B tile: 32 k x 64 n = 512 float4, 4 per thread ----
        #pragma unroll
        for (int i = 0; i < 4; i++) {
            int idx = tid + i * 128;
            int kr   = idx >> 4;          // 0..31
            int cseg = idx & 15;          // 0..15 (n/4)
            float4 v = *(const float4*)(B + (size_t)(k0 + kr) * Nn + bn + cseg * 4);
            uint4 u;
            u.x = f2tf32(v.x); u.y = f2tf32(v.y); u.z = f2tf32(v.z); u.w = f2tf32(v.w);
            *(uint4*)(&Bs[kr * BSP + cseg * 4]) = u;
        }
        __syncthreads();

        #pragma unroll
        for (int q = 0; q < 4; q++) {
            int kb = q * 8;
            unsigned af[2][4];
            #pragma unroll
            for (int mi = 0; mi < 2; mi++) {
                int rb = wm * 32 + mi * 16;
                af[mi][0] = As[(rb + g)     * ASP + kb + tig];
                af[mi][1] = As[(rb + g + 8) * ASP + kb + tig];
                af[mi][2] = As[(rb + g)     * ASP + kb + tig + 4];
                af[mi][3] = As[(rb + g + 8) * ASP + kb + tig + 4];
            }
            #pragma unroll
            for (int ni = 0; ni < 4; ni++) {
                int cb = wn * 32 + ni * 8 + g;
                unsigned b0 = Bs[(kb + tig)     * BSP + cb];
                unsigned b1 = Bs[(kb + tig + 4) * BSP + cb];
                mma_tf32(acc[0][ni], af[0], b0, b1);
                mma_tf32(acc[1][ni], af[1], b0, b1);
            }
        }
        __syncthreads();
    }

    // ---- epilogue ----
    #pragma unroll
    for (int mi = 0; mi < 2; mi++) {
        int row0 = bm + wm * 32 + mi * 16 + g;
        #pragma unroll
        for (int ni = 0; ni < 4; ni++) {
            int col = bn + wn * 32 + ni * 8 + tig * 2;
            float bx = 0.f, by = 0.f;
            if (EPI != 0) { bx = bias[col]; by = bias[col + 1]; }
            // rows row0 and row0+8
            #pragma unroll
            for (int rr = 0; rr < 2; rr++) {
                int row = row0 + rr * 8;
                if (row >= M) continue;
                float o0 = acc[mi][ni][rr * 2 + 0];
                float o1 = acc[mi][ni][rr * 2 + 1];
                if (EPI == 1) {
                    o0 = gelu_exact(o0 + bx);
                    o1 = gelu_exact(o1 + by);
                } else if (EPI == 2) {
                    const float2 r2 = *(const float2*)(Cres + (size_t)row * Nn + col);
                    o0 += bx + r2.x;
                    o1 += by + r2.y;
                }
                float2 o2 = make_float2(o0, o1);
                *(float2*)(C + (size_t)row * Nn + col) = o2;
            }
        }
    }
}

// -------------------- kernel: attention + residual + LN + LN2 (fused) --------------------
__global__ void attn_kernel(const float* __restrict__ val, const float* __restrict__ st_in,
                            const float* __restrict__ qk, float* __restrict__ val_out,
                            float* __restrict__ x_out, float* __restrict__ st_out,
                            const float* __restrict__ gate_arr, int l,
                            const float* __restrict__ lng, const float* __restrict__ lnb,
                            const float* __restrict__ ln2g, const float* __restrict__ ln2b) {
    __shared__ float s_q[128];
    __shared__ float s_a[K_];
    __shared__ int   s_j[K_];    // -1 encodes invalid
    __shared__ float s_e[K_];
    __shared__ float red[4];

    int n = blockIdx.x;
    int tid = threadIdx.x;
    int lane = tid & 31, wid = tid >> 5;
    float gate = gate_arr[l];

    s_q[tid] = qk[(size_t)n * 256 + tid];
    __syncthreads();

    const float scale = 0.17677669529663687f; // 1/sqrt(32)

    // ---- phase 1: per-neighbor head scores, head softmax, aggregate a ----
    for (int kk = wid; kk < K_; kk += 4) {
        int j; bool valid;
        if (kk == 0) { j = 0; valid = (n > W_); }
        else { int raw = n - (W_ + 1) + kk; valid = (raw >= 0); j = raw > 0 ? raw : 0; }
        const float* krow = qk + (size_t)j * 256 + 128;
        float p0 = s_q[lane]      * __ldg(krow + lane);
        float p1 = s_q[32 + lane] * __ldg(krow + 32 + lane);
        float p2 = s_q[64 + lane] * __ldg(krow + 64 + lane);
        float p3 = s_q[96 + lane] * __ldg(krow + 96 + lane);
        #pragma unroll
        for (int o = 16; o > 0; o >>= 1) {
            p0 += __shfl_xor_sync(0xffffffffu, p0, o);
            p1 += __shfl_xor_sync(0xffffffffu, p1, o);
            p2 += __shfl_xor_sync(0xffffffffu, p2, o);
            p3 += __shfl_xor_sync(0xffffffffu, p3, o);
        }
        if (lane == 0) {
            float s0 = p0 * scale, s1 = p1 * scale, s2 = p2 * scale, s3 = p3 * scale;
            float a0 = fabsf(s0), a1 = fabsf(s1), a2 = fabsf(s2), a3 = fabsf(s3);
            float m = fmaxf(fmaxf(a0, a1), fmaxf(a2, a3));
            float e0 = __expf(a0 - m), e1 = __expf(a1 - m), e2 = __expf(a2 - m), e3 = __expf(a3 - m);
            float den = e0 + e1 + e2 + e3;
            s_a[kk] = (s0 * e0 + s1 * e1 + s2 * e2 + s3 * e3) / den;
            s_j[kk] = valid ? j : -1;
        }
    }
    __syncthreads();

    // ---- phase 2: signed softmax over neighbors, times gathered state ----
    float a0v = s_a[tid]; int j0 = s_j[tid];
    float ab0 = (j0 >= 0) ? fabsf(a0v) : -1e30f;
    float a1v = 0.f; int j1 = -1; float ab1 = -1e30f;
    if (tid < K_ - 128) { a1v = s_a[128 + tid]; j1 = s_j[128 + tid]; ab1 = (j1 >= 0) ? fabsf(a1v) : -1e30f; }
    float mx = blkMax128(fmaxf(ab0, ab1), red);
    float e0 = (j0 >= 0) ? __expf(ab0 - mx) : 0.f;
    float e1 = (j1 >= 0) ? __expf(ab1 - mx) : 0.f;
    float inv = 1.0f / blkSum128(e0 + e1, red);

    float ds = 0.f;
    {
        float sg0 = (a0v > 0.f) ? 1.f : ((a0v < 0.f) ? -1.f : 0.f);
        float ee0 = (j0 >= 0) ? e0 * inv * sg0 * __ldg(st_in + j0) : 0.f;
        s_e[tid] = ee0; ds += ee0;
        if (tid < K_ - 128) {
            float sg1 = (a1v > 0.f) ? 1.f : ((a1v < 0.f) ? -1.f : 0.f);
            float ee1 = (j1 >= 0) ? e1 * inv * sg1 * __ldg(st_in + j1) : 0.f;
            s_e[128 + tid] = ee1; ds += ee1;
        }
    }
    float d_state = blkSum128(ds, red);  // internal syncthreads also publishes s_e

    // ---- phase 3: d_val gather, residual, LN, LN2 ----
    const float4* val4 = (const float4*)val;
    float4 acc = make_float4(0.f, 0.f, 0.f, 0.f);
    for (int kk = 0; kk < K_; kk++) {
        float e = s_e[kk];
        if (e != 0.f) {
            int j = s_j[kk];
            float4 v = __ldg(&val4[(size_t)j * 128 + tid]);
            acc.x = fmaf(e, v.x, acc.x);
            acc.y = fmaf(e, v.y, acc.y);
            acc.z = fmaf(e, v.z, acc.z);
            acc.w = fmaf(e, v.w, acc.w);
        }
    }
    float4 cur = val4[(size_t)n * 128 + tid];
    float x0 = cur.x + gate * acc.x;
    float x1 = cur.y + gate * acc.y;
    float x2 = cur.z + gate * acc.z;
    float x3 = cur.w + gate * acc.w;

    float s  = blkSum128(x0 + x1 + x2 + x3, red);
    float sq = blkSum128(x0*x0 + x1*x1 + x2*x2 + x3*x3, red);
    float mean = s * (1.0f / D_);
    float var  = sq * (1.0f / D_) - mean * mean;
    float rstd = rsqrtf(var + 1e-5f);
    float4 g4 = ((const float4*)lng)[tid], b4 = ((const float4*)lnb)[tid];
    float y0 = (x0 - mean) * rstd * g4.x + b4.x;
    float y1 = (x1 - mean) * rstd * g4.y + b4.y;
    float y2 = (x2 - mean) * rstd * g4.z + b4.z;
    float y3 = (x3 - mean) * rstd * g4.w + b4.w;
    ((float4*)val_out)[(size_t)n * 128 + tid] = make_float4(y0, y1, y2, y3);

    // second LN (ln2) fused -> FFN input
    float s2  = blkSum128(y0 + y1 + y2 + y3, red);
    float sq2 = blkSum128(y0*y0 + y1*y1 + y2*y2 + y3*y3, red);
    float mean2 = s2 * (1.0f / D_);
    float var2  = sq2 * (1.0f / D_) - mean2 * mean2;
    float rstd2 = rsqrtf(var2 + 1e-5f);
    float4 g24 = ((const float4*)ln2g)[tid], b24 = ((const float4*)ln2b)[tid];
    float4 xo;
    xo.x = (y0 - mean2) * rstd2 * g24.x + b24.x;
    xo.y = (y1 - mean2) * rstd2 * g24.y + b24.y;
    xo.z = (y2 - mean2) * rstd2 * g24.z + b24.z;
    xo.w = (y3 - mean2) * rstd2 * g24.w + b24.w;
    ((float4*)x_out)[(size_t)n * 128 + tid] = xo;

    if (tid == 0) st_out[n] = st_in[n] + gate * d_state;
}

// -------------------- launch --------------------
extern "C" void kernel_launch(void* const* d_in, const int* in_sizes, int n_in,
                              void* d_out, int out_size) {
    const int*   ids     = (const int*)d_in[0];
    const float* embed   = (const float*)d_in[1];
    const float* pos     = (const float*)d_in[2];
    const float* ln_in_g = (const float*)d_in[3];
    const float* ln_in_b = (const float*)d_in[4];
    const float* anc_st  = (const float*)d_in[5];
    const float* anc_val = (const float*)d_in[6];
    const float* state_w = (const float*)d_in[7];
    const float* state_b = (const float*)d_in[8];
    const float* wq      = (const float*)d_in[9];
    const float* wk      = (const float*)d_in[10];
    const float* gate    = (const float*)d_in[11];
    const float* ln_g    = (const float*)d_in[12];
    const float* ln_b    = (const float*)d_in[13];
    const float* ffn_w1  = (const float*)d_in[14];
    const float* ffn_b1  = (const float*)d_in[15];
    const float* ffn_w2  = (const float*)d_in[16];
    const float* ffn_b2  = (const float*)d_in[17];
    const float* ln2_g   = (const float*)d_in[18];
    const float* ln2_b   = (const float*)d_in[19];
    float* out = (float*)d_out;

    float *valA, *valB, *x, *h, *qk, *stA, *stB, *wqk;
    cudaGetSymbolAddress((void**)&valA, g_valA);
    cudaGetSymbolAddress((void**)&valB, g_valB);
    cudaGetSymbolAddress((void**)&x,    g_x);
    cudaGetSymbolAddress((void**)&h,    g_h);
    cudaGetSymbolAddress((void**)&qk,   g_qk);
    cudaGetSymbolAddress((void**)&stA,  g_stA);
    cudaGetSymbolAddress((void**)&stB,  g_stB);
    cudaGetSymbolAddress((void**)&wqk,  g_wqk);

    prep_wqk_kernel<<<(L_ * D_ * 256) / 256, 256>>>(wq, wk, wqk);
    embed_ln_kernel<<<N_, 128>>>(ids, embed, pos, ln_in_g, ln_in_b, anc_val, anc_st,
                                 state_w, state_b, valA, stA);

    float* s_in = stA;
    float* s_out = stB;
    const int MB = (N_ + GBM - 1) / GBM;   // 25
    for (int l = 0; l < L_; l++) {
        dim3 gqk(MB, 256 / GBN);
        mma_gemm_kernel<0><<<gqk, 128>>>(valA, wqk + (size_t)l * D_ * 256, qk,
                                         nullptr, nullptr, N_, 256, D_);
        attn_kernel<<<N_, 128>>>(valA, s_in, qk, valB, x, s_out, gate, l,
                                 ln_g + l * D_, ln_b + l * D_,
                                 ln2_g + l * D_, ln2_b + l * D_);
        dim3 g1(MB, HFF_ / GBN);
        mma_gemm_kernel<1><<<g1, 128>>>(x, ffn_w1 + (size_t)l * D_ * HFF_, h,
                                        ffn_b1 + l * HFF_, nullptr, N_, HFF_, D_);
        float* dst = (l == L_ - 1) ? out : valA;
        dim3 g2(MB, D_ / GBN);
        mma_gemm_kernel<2><<<g2, 128>>>(h, ffn_w2 + (size_t)l * HFF_ * D_, dst,
                                        ffn_b2 + l * D_, valB, N_, D_, HFF_);
        float* t = s_in; s_in = s_out; s_out = t;
    }
}

// round 15
// speedup vs baseline: 1.4469x; 1.0054x over previous
#include <cuda_runtime.h>
#include <math.h>
#include <cuda_bf16.h>

// Problem constants
#define S_  1536
#define N_  1537          // S + 1 (anchor row 0)
#define D_  512
#define H_  4
#define R_  32
#define HR_ 128           // H*R
#define W_  128
#define K_  130           // W + 2
#define HFF_ 1024
#define L_  4

// -------------------- device scratch (no allocations allowed) --------------------
__device__ float g_valA[N_ * D_];
__device__ float g_valB[N_ * D_];
__device__ float g_x[N_ * D_];       // ln2(valB), FFN GEMM1 input
__device__ float g_h[N_ * HFF_];     // FFN hidden
__device__ float g_qk[N_ * 256];     // [n][0:128]=q(h*R+r), [128:256]=k
__device__ float g_stA[N_];
__device__ float g_stB[N_];
__device__ float g_wqk[L_ * D_ * 256]; // transposed wq|wk per layer: [(l*D+d)*256 + c]

// -------------------- helpers --------------------
__device__ __forceinline__ float gelu_exact(float x) {
    return 0.5f * x * (1.0f + erff(x * 0.7071067811865475f));
}

__device__ __forceinline__ unsigned f2tf32(float f) {
    unsigned u;
    asm("cvt.rna.tf32.f32 %0, %1;" : "=r"(u) : "f"(f));
    return u;
}

__device__ __forceinline__ void mma_tf32(float* c, const unsigned* a, unsigned b0, unsigned b1) {
    asm volatile(
        "mma.sync.aligned.m16n8k8.row.col.f32.tf32.tf32.f32 "
        "{%0,%1,%2,%3}, {%4,%5,%6,%7}, {%8,%9}, {%0,%1,%2,%3};\n"
        : "+f"(c[0]), "+f"(c[1]), "+f"(c[2]), "+f"(c[3])
        : "r"(a[0]), "r"(a[1]), "r"(a[2]), "r"(a[3]), "r"(b0), "r"(b1));
}

// block reductions for 128-thread blocks (4 warps)
__device__ __forceinline__ float blkSum128(float v, volatile float* red) {
    #pragma unroll
    for (int o = 16; o > 0; o >>= 1) v += __shfl_xor_sync(0xffffffffu, v, o);
    __syncthreads();
    if ((threadIdx.x & 31) == 0) red[threadIdx.x >> 5] = v;
    __syncthreads();
    return red[0] + red[1] + red[2] + red[3];
}
__device__ __forceinline__ float blkMax128(float v, volatile float* red) {
    #pragma unroll
    for (int o = 16; o > 0; o >>= 1) v = fmaxf(v, __shfl_xor_sync(0xffffffffu, v, o));
    __syncthreads();
    if ((threadIdx.x & 31) == 0) red[threadIdx.x >> 5] = v;
    __syncthreads();
    return fmaxf(fmaxf(red[0], red[1]), fmaxf(red[2], red[3]));
}

// -------------------- kernel: transpose wq/wk into GEMM-friendly layout --------------------
__global__ void prep_wqk_kernel(const float* __restrict__ wq, const float* __restrict__ wk,
                                float* __restrict__ out) {
    int i = blockIdx.x * blockDim.x + threadIdx.x;      // 0 .. 2^19-1
    int c = i & 255;
    int d = (i >> 8) & 511;
    int l = i >> 17;
    const float* w = (c < 128) ? wq : wk;
    int cc = c & 127;
    int h  = cc >> 5;
    int r  = cc & 31;
    out[i] = w[(((l * H_ + h) * D_ + d) * R_) + r];
}

// -------------------- kernel: embedding + input LN + state init --------------------
__global__ void embed_ln_kernel(const int* __restrict__ ids, const float* __restrict__ emb,
                                const float* __restrict__ pos, const float* __restrict__ g,
                                const float* __restrict__ b, const float* __restrict__ av,
                                const float* __restrict__ ast, const float* __restrict__ sw,
                                const float* __restrict__ sb, float* __restrict__ val,
                                float* __restrict__ st) {
    __shared__ float red[4];
    int n = blockIdx.x, tid = threadIdx.x;   // 128 threads, float4 per thread
    float4* val4 = (float4*)val;
    if (n == 0) {
        val4[tid] = ((const float4*)av)[tid];   // anchor row: raw anchor_val (no LN)
        if (tid == 0) st[0] = ast[0];
        return;
    }
    int t = n - 1;
    int id = ids[t];
    float4 e4 = ((const float4*)(emb + (size_t)id * D_))[tid];
    float4 p4 = ((const float4*)(pos + (size_t)t  * D_))[tid];
    float x0 = e4.x + p4.x, x1 = e4.y + p4.y, x2 = e4.z + p4.z, x3 = e4.w + p4.w;
    float s  = blkSum128(x0 + x1 + x2 + x3, red);
    float sq = blkSum128(x0*x0 + x1*x1 + x2*x2 + x3*x3, red);
    float mean = s * (1.0f / D_);
    float var  = sq * (1.0f / D_) - mean * mean;
    float rstd = rsqrtf(var + 1e-5f);
    float4 g4 = ((const float4*)g)[tid], b4 = ((const float4*)b)[tid];
    float4 y;
    y.x = (x0 - mean) * rstd * g4.x + b4.x;
    y.y = (x1 - mean) * rstd * g4.y + b4.y;
    y.z = (x2 - mean) * rstd * g4.z + b4.z;
    y.w = (x3 - mean) * rstd * g4.w + b4.w;
    val4[(size_t)n * 128 + tid] = y;
    float4 w4 = ((const float4*)sw)[tid];
    float dot = blkSum128(y.x*w4.x + y.y*w4.y + y.z*w4.z + y.w*w4.w, red);
    if (tid == 0) st[n] = dot + sb[0];
}

// -------------------- kernel: tf32 tensor-core GEMM --------------------
// C(MxN) = A(MxK) @ B(KxN); A,B row-major fp32 (converted to tf32 in smem).
// Block tile 64x64x32, 128 threads (4 warps, 2x2 warp grid, 32x32 warp tile).
// EPI 0: plain; 1: gelu(AB + bias); 2: AB + bias + Cres
#define GBM 64
#define GBN 64
#define GBK 32
#define ASP 36   // padded A row stride (k-dim 32 + 4)
#define BSP 72   // padded B row stride (n-dim 64 + 8)

template <int EPI>
__global__ __launch_bounds__(128) void mma_gemm_kernel(
        const float* __restrict__ A, const float* __restrict__ B,
        float* __restrict__ C, const float* __restrict__ bias,
        const float* __restrict__ Cres, int M, int Nn, int Kk) {
    __shared__ unsigned As[GBM * ASP];   // As[row][k]
    __shared__ unsigned Bs[GBK * BSP];   // Bs[k][n]

    int tid  = threadIdx.x;
    int lane = tid & 31;
    int wid  = tid >> 5;          // 0..3
    int wm   = wid & 1;           // warp row (2)
    int wn   = wid >> 1;          // warp col (2)
    int g    = lane >> 2;         // groupID 0..7
    int tig  = lane & 3;          // thread-in-group 0..3

    int bm = blockIdx.x * GBM;
    int bn = blockIdx.y * GBN;

    float acc[2][4][4];
    #pragma unroll
    for (int i = 0; i < 2; i++)
        #pragma unroll
        for (int j = 0; j < 4; j++)
            #pragma unroll
            for (int c = 0; c < 4; c++) acc[i][j][c] = 0.f;

    const int KT = Kk / GBK;
    for (int kt = 0; kt < KT; kt++) {
        int k0 = kt * GBK;
        // ---- load A tile: 64 rows x 32 k = 512 float4, 4 per thread ----
        #pragma unroll
        for (int i = 0; i < 4; i++) {
            int idx = tid + i * 128;
            int row = idx >> 3;          // 0..63
            int seg = idx & 7;           // 0..7 (k/4)
            float4 v = make_float4(0.f, 0.f, 0.f, 0.f);
            if (bm + row < M)
                v = *(const float4*)(A + (size_t)(bm + row) * Kk + k0 + seg * 4);
            uint4 u;
            u.x = f2tf32(v.x); u.y = f2tf32(v.y); u.z = f2tf32(v.z); u.w = f2tf32(v.w);
            *(uint4*)(&As[row * ASP + seg * 4]) = u;
        }
        // ---- load B tile: 32 k x 64 n = 512 float4, 4 per thread ----
        #pragma unroll
        for (int i = 0; i < 4; i++) {
            int idx = tid + i * 128;
            int kr   = idx >> 4;          // 0..31
            int cseg = idx & 15;          // 0..15 (n/4)
            float4 v = *(const float4*)(B + (size_t)(k0 + kr) * Nn + bn + cseg * 4);
            uint4 u;
            u.x = f2tf32(v.x); u.y = f2tf32(v.y); u.z = f2tf32(v.z); u.w = f2tf32(v.w);
            *(uint4*)(&Bs[kr * BSP + cseg * 4]) = u;
        }
        __syncthreads();

        #pragma unroll
        for (int q = 0; q < 4; q++) {
            int kb = q * 8;
            unsigned af[2][4];
            #pragma unroll
            for (int mi = 0; mi < 2; mi++) {
                int rb = wm * 32 + mi * 16;
                af[mi][0] = As[(rb + g)     * ASP + kb + tig];
                af[mi][1] = As[(rb + g + 8) * ASP + kb + tig];
                af[mi][2] = As[(rb + g)     * ASP + kb + tig + 4];
                af[mi][3] = As[(rb + g + 8) * ASP + kb + tig + 4];
            }
            #pragma unroll
            for (int ni = 0; ni < 4; ni++) {
                int cb = wn * 32 + ni * 8 + g;
                unsigned b0 = Bs[(kb + tig)     * BSP + cb];
                unsigned b1 = Bs[(kb + tig + 4) * BSP + cb];
                mma_tf32(acc[0][ni], af[0], b0, b1);
                mma_tf32(acc[1][ni], af[1], b0, b1);
            }
        }
        __syncthreads();
    }

    // ---- epilogue ----
    #pragma unroll
    for (int mi = 0; mi < 2; mi++) {
        int row0 = bm + wm * 32 + mi * 16 + g;
        #pragma unroll
        for (int ni = 0; ni < 4; ni++) {
            int col = bn + wn * 32 + ni * 8 + tig * 2;
            float bx = 0.f, by = 0.f;
            if (EPI != 0) { bx = bias[col]; by = bias[col + 1]; }
            // rows row0 and row0+8
            #pragma unroll
            for (int rr = 0; rr < 2; rr++) {
                int row = row0 + rr * 8;
                if (row >= M) continue;
                float o0 = acc[mi][ni][rr * 2 + 0];
                float o1 = acc[mi][ni][rr * 2 + 1];
                if (EPI == 1) {
                    o0 = gelu_exact(o0 + bx);
                    o1 = gelu_exact(o1 + by);
                } else if (EPI == 2) {
                    const float2 r2 = *(const float2*)(Cres + (size_t)row * Nn + col);
                    o0 += bx + r2.x;
                    o1 += by + r2.y;
                }
                float2 o2 = make_float2(o0, o1);
                *(float2*)(C + (size_t)row * Nn + col) = o2;
            }
        }
    }
}

// -------------------- kernel: attention + residual + LN + LN2 (fused) --------------------
__global__ void attn_kernel(const float* __restrict__ val, const float* __restrict__ st_in,
                            const float* __restrict__ qk, float* __restrict__ val_out,
                            float* __restrict__ x_out, float* __restrict__ st_out,
                            const float* __restrict__ gate_arr, int l,
                            const float* __restrict__ lng, const float* __restrict__ lnb,
                            const float* __restrict__ ln2g, const float* __restrict__ ln2b) {
    __shared__ float s_q[128];
    __shared__ float s_a[K_];
    __shared__ int   s_j[K_];    // -1 encodes invalid
    __shared__ float s_e[K_];
    __shared__ float red[4];

    int n = blockIdx.x;
    int tid = threadIdx.x;
    int lane = tid & 31, wid = tid >> 5;
    float gate = gate_arr[l];

    s_q[tid] = qk[(size_t)n * 256 + tid];
    __syncthreads();

    const float scale = 0.17677669529663687f; // 1/sqrt(32)

    // ---- phase 1: per-neighbor head scores, head softmax, aggregate a ----
    for (int kk = wid; kk < K_; kk += 4) {
        int j; bool valid;
        if (kk == 0) { j = 0; valid = (n > W_); }
        else { int raw = n - (W_ + 1) + kk; valid = (raw >= 0); j = raw > 0 ? raw : 0; }
        const float* krow = qk + (size_t)j * 256 + 128;
        float p0 = s_q[lane]      * __ldg(krow + lane);
        float p1 = s_q[32 + lane] * __ldg(krow + 32 + lane);
        float p2 = s_q[64 + lane] * __ldg(krow + 64 + lane);
        float p3 = s_q[96 + lane] * __ldg(krow + 96 + lane);
        #pragma unroll
        for (int o = 16; o > 0; o >>= 1) {
            p0 += __shfl_xor_sync(0xffffffffu, p0, o);
            p1 += __shfl_xor_sync(0xffffffffu, p1, o);
            p2 += __shfl_xor_sync(0xffffffffu, p2, o);
            p3 += __shfl_xor_sync(0xffffffffu, p3, o);
        }
        if (lane == 0) {
            float s0 = p0 * scale, s1 = p1 * scale, s2 = p2 * scale, s3 = p3 * scale;
            float a0 = fabsf(s0), a1 = fabsf(s1), a2 = fabsf(s2), a3 = fabsf(s3);
            float m = fmaxf(fmaxf(a0, a1), fmaxf(a2, a3));
            float e0 = __expf(a0 - m), e1 = __expf(a1 - m), e2 = __expf(a2 - m), e3 = __expf(a3 - m);
            float den = e0 + e1 + e2 + e3;
            s_a[kk] = (s0 * e0 + s1 * e1 + s2 * e2 + s3 * e3) / den;
            s_j[kk] = valid ? j : -1;
        }
    }
    __syncthreads();

    // ---- phase 2: signed softmax over neighbors, times gathered state ----
    float a0v = s_a[tid]; int j0 = s_j[tid];
    float ab0 = (j0 >= 0) ? fabsf(a0v) : -1e30f;
    float a1v = 0.f; int j1 = -1; float ab1 = -1e30f;
    if (tid < K_ - 128) { a1v = s_a[128 + tid]; j1 = s_j[128 + tid]; ab1 = (j1 >= 0) ? fabsf(a1v) : -1e30f; }
    float mx = blkMax128(fmaxf(ab0, ab1), red);
    float e0 = (j0 >= 0) ? __expf(ab0 - mx) : 0.f;
    float e1 = (j1 >= 0) ? __expf(ab1 - mx) : 0.f;
    float inv = 1.0f / blkSum128(e0 + e1, red);

    float ds = 0.f;
    {
        float sg0 = (a0v > 0.f) ? 1.f : ((a0v < 0.f) ? -1.f : 0.f);
        float ee0 = (j0 >= 0) ? e0 * inv * sg0 * __ldg(st_in + j0) : 0.f;
        s_e[tid] = ee0; ds += ee0;
        if (tid < K_ - 128) {
            float sg1 = (a1v > 0.f) ? 1.f : ((a1v < 0.f) ? -1.f : 0.f);
            float ee1 = (j1 >= 0) ? e1 * inv * sg1 * __ldg(st_in + j1) : 0.f;
            s_e[128 + tid] = ee1; ds += ee1;
        }
    }
    float d_state = blkSum128(ds, red);  // internal syncthreads also publishes s_e

    // ---- phase 3: d_val gather, residual, LN, LN2 ----
    const float4* val4 = (const float4*)val;
    float4 acc = make_float4(0.f, 0.f, 0.f, 0.f);
    for (int kk = 0; kk < K_; kk++) {
        float e = s_e[kk];
        if (e != 0.f) {
            int j = s_j[kk];
            float4 v = __ldg(&val4[(size_t)j * 128 + tid]);
            acc.x = fmaf(e, v.x, acc.x);
            acc.y = fmaf(e, v.y, acc.y);
            acc.z = fmaf(e, v.z, acc.z);
            acc.w = fmaf(e, v.w, acc.w);
        }
    }
    float4 cur = val4[(size_t)n * 128 + tid];
    float x0 = cur.x + gate * acc.x;
    float x1 = cur.y + gate * acc.y;
    float x2 = cur.z + gate * acc.z;
    float x3 = cur.w + gate * acc.w;

    float s  = blkSum128(x0 + x1 + x2 + x3, red);
    float sq = blkSum128(x0*x0 + x1*x1 + x2*x2 + x3*x3, red);
    float mean = s * (1.0f / D_);
    float var  = sq * (1.0f / D_) - mean * mean;
    float rstd = rsqrtf(var + 1e-5f);
    float4 g4 = ((const float4*)lng)[tid], b4 = ((const float4*)lnb)[tid];
    float y0 = (x0 - mean) * rstd * g4.x + b4.x;
    float y1 = (x1 - mean) * rstd * g4.y + b4.y;
    float y2 = (x2 - mean) * rstd * g4.z + b4.z;
    float y3 = (x3 - mean) * rstd * g4.w + b4.w;
    ((float4*)val_out)[(size_t)n * 128 + tid] = make_float4(y0, y1, y2, y3);

    // second LN (ln2) fused -> FFN input
    float s2  = blkSum128(y0 + y1 + y2 + y3, red);
    float sq2 = blkSum128(y0*y0 + y1*y1 + y2*y2 + y3*y3, red);
    float mean2 = s2 * (1.0f / D_);
    float var2  = sq2 * (1.0f / D_) - mean2 * mean2;
    float rstd2 = rsqrtf(var2 + 1e-5f);
    float4 g24 = ((const float4*)ln2g)[tid], b24 = ((const float4*)ln2b)[tid];
    float4 xo;
    xo.x = (y0 - mean2) * rstd2 * g24.x + b24.x;
    xo.y = (y1 - mean2) * rstd2 * g24.y + b24.y;
    xo.z = (y2 - mean2) * rstd2 * g24.z + b24.z;
    xo.w = (y3 - mean2) * rstd2 * g24.w + b24.w;
    ((float4*)x_out)[(size_t)n * 128 + tid] = xo;

    if (tid == 0) st_out[n] = st_in[n] + gate * d_state;
}

// -------------------- launch --------------------
extern "C" void kernel_launch(void* const* d_in, const int* in_sizes, int n_in,
                              void* d_out, int out_size) {
    const int*   ids     = (const int*)d_in[0];
    const float* embed   = (const float*)d_in[1];
    const float* pos     = (const float*)d_in[2];
    const float* ln_in_g = (const float*)d_in[3];
    const float* ln_in_b = (const float*)d_in[4];
    const float* anc_st  = (const float*)d_in[5];
    const float* anc_val = (const float*)d_in[6];
    const float* state_w = (const float*)d_in[7];
    const float* state_b = (const float*)d_in[8];
    const float* wq      = (const float*)d_in[9];
    const float* wk      = (const float*)d_in[10];
    const float* gate    = (const float*)d_in[11];
    const float* ln_g    = (const float*)d_in[12];
    const float* ln_b    = (const float*)d_in[13];
    const float* ffn_w1  = (const float*)d_in[14];
    const float* ffn_b1  = (const float*)d_in[15];
    const float* ffn_w2  = (const float*)d_in[16];
    const float* ffn_b2  = (const float*)d_in[17];
    const float* ln2_g   = (const float*)d_in[18];
    const float* ln2_b   = (const float*)d_in[19];
    float* out = (float*)d_out;

    float *valA, *valB, *x, *h, *qk, *stA, *stB, *wqk;
    cudaGetSymbolAddress((void**)&valA, g_valA);
    cudaGetSymbolAddress((void**)&valB, g_valB);
    cudaGetSymbolAddress((void**)&x,    g_x);
    cudaGetSymbolAddress((void**)&h,    g_h);
    cudaGetSymbolAddress((void**)&qk,   g_qk);
    cudaGetSymbolAddress((void**)&stA,  g_stA);
    cudaGetSymbolAddress((void**)&stB,  g_stB);
    cudaGetSymbolAddress((void**)&wqk,  g_wqk);

    prep_wqk_kernel<<<(L_ * D_ * 256) / 256, 256>>>(wq, wk, wqk);
    embed_ln_kernel<<<N_, 128>>>(ids, embed, pos, ln_in_g, ln_in_b, anc_val, anc_st,
                                 state_w, state_b, valA, stA);

    float* s_in = stA;
    float* s_out = stB;
    const int MB = (N_ + GBM - 1) / GBM;   // 25
    for (int l = 0; l < L_; l++) {
        dim3 gqk(MB, 256 / GBN);
        mma_gemm_kernel<0><<<gqk, 128>>>(valA, wqk + (size_t)l * D_ * 256, qk,
                                         nullptr, nullptr, N_, 256, D_);
        attn_kernel<<<N_, 128>>>(valA, s_in, qk, valB, x, s_out, gate, l,
                                 ln_g + l * D_, ln_b + l * D_,
                                 ln2_g + l * D_, ln2_b + l * D_);
        dim3 g1(MB, HFF_ / GBN);
        mma_gemm_kernel<1><<<g1, 128>>>(x, ffn_w1 + (size_t)l * D_ * HFF_, h,
                                        ffn_b1 + l * HFF_, nullptr, N_, HFF_, D_);
        float* dst = (l == L_ - 1) ? out : valA;
        dim3 g2(MB, D_ / GBN);
        mma_gemm_kernel<2><<<g2, 128>>>(h, ffn_w2 + (size_t)l * HFF_ * D_, dst,
                                        ffn_b2 + l * D_, valB, N_, D_, HFF_);
        float* t = s_in; s_in = s_out; s_out = t;
    }
}

// round 16
// speedup vs baseline: 1.4534x; 1.0045x over previous
#include <cuda_runtime.h>
#include <math.h>
#include <cuda_bf16.h>

// Problem constants
#define S_  1536
#define N_  1537          // S + 1 (anchor row 0)
#define D_  512
#define H_  4
#define R_  32
#define HR_ 128           // H*R
#define W_  128
#define K_  130           // W + 2
#define HFF_ 1024
#define L_  4

// -------------------- device scratch (no allocations allowed) --------------------
__device__ float g_valA[N_ * D_];
__device__ float g_valB[N_ * D_];
__device__ float g_x[N_ * D_];       // ln2(valB), FFN GEMM1 input
__device__ float g_h[N_ * HFF_];     // FFN hidden
__device__ float g_qk[N_ * 256];     // [n][0:128]=q(h*R+r), [128:256]=k
__device__ float g_stA[N_];
__device__ float g_stB[N_];
__device__ float g_wqk[L_ * D_ * 256]; // transposed wq|wk per layer: [(l*D+d)*256 + c]

// -------------------- helpers --------------------
__device__ __forceinline__ float gelu_exact(float x) {
    return 0.5f * x * (1.0f + erff(x * 0.7071067811865475f));
}

__device__ __forceinline__ unsigned f2tf32(float f) {
    unsigned u;
    asm("cvt.rna.tf32.f32 %0, %1;" : "=r"(u) : "f"(f));
    return u;
}

__device__ __forceinline__ void mma_tf32(float* c, const unsigned* a, unsigned b0, unsigned b1) {
    asm volatile(
        "mma.sync.aligned.m16n8k8.row.col.f32.tf32.tf32.f32 "
        "{%0,%1,%2,%3}, {%4,%5,%6,%7}, {%8,%9}, {%0,%1,%2,%3};\n"
        : "+f"(c[0]), "+f"(c[1]), "+f"(c[2]), "+f"(c[3])
        : "r"(a[0]), "r"(a[1]), "r"(a[2]), "r"(a[3]), "r"(b0), "r"(b1));
}

// block reductions for 128-thread blocks (4 warps)
__device__ __forceinline__ float blkSum128(float v, volatile float* red) {
    #pragma unroll
    for (int o = 16; o > 0; o >>= 1) v += __shfl_xor_sync(0xffffffffu, v, o);
    __syncthreads();
    if ((threadIdx.x & 31) == 0) red[threadIdx.x >> 5] = v;
    __syncthreads();
    return red[0] + red[1] + red[2] + red[3];
}
__device__ __forceinline__ float blkMax128(float v, volatile float* red) {
    #pragma unroll
    for (int o = 16; o > 0; o >>= 1) v = fmaxf(v, __shfl_xor_sync(0xffffffffu, v, o));
    __syncthreads();
    if ((threadIdx.x & 31) == 0) red[threadIdx.x >> 5] = v;
    __syncthreads();
    return fmaxf(fmaxf(red[0], red[1]), fmaxf(red[2], red[3]));
}

// -------------------- kernel: transpose wq/wk into GEMM-friendly layout --------------------
__global__ void prep_wqk_kernel(const float* __restrict__ wq, const float* __restrict__ wk,
                                float* __restrict__ out) {
    int i = blockIdx.x * blockDim.x + threadIdx.x;      // 0 .. 2^19-1
    int c = i & 255;
    int d = (i >> 8) & 511;
    int l = i >> 17;
    const float* w = (c < 128) ? wq : wk;
    int cc = c & 127;
    int h  = cc >> 5;
    int r  = cc & 31;
    out[i] = w[(((l * H_ + h) * D_ + d) * R_) + r];
}

// -------------------- kernel: embedding + input LN + state init --------------------
__global__ void embed_ln_kernel(const int* __restrict__ ids, const float* __restrict__ emb,
                                const float* __restrict__ pos, const float* __restrict__ g,
                                const float* __restrict__ b, const float* __restrict__ av,
                                const float* __restrict__ ast, const float* __restrict__ sw,
                                const float* __restrict__ sb, float* __restrict__ val,
                                float* __restrict__ st) {
    __shared__ float red[4];
    int n = blockIdx.x, tid = threadIdx.x;   // 128 threads, float4 per thread
    float4* val4 = (float4*)val;
    if (n == 0) {
        val4[tid] = ((const float4*)av)[tid];   // anchor row: raw anchor_val (no LN)
        if (tid == 0) st[0] = ast[0];
        return;
    }
    int t = n - 1;
    int id = ids[t];
    float4 e4 = ((const float4*)(emb + (size_t)id * D_))[tid];
    float4 p4 = ((const float4*)(pos + (size_t)t  * D_))[tid];
    float x0 = e4.x + p4.x, x1 = e4.y + p4.y, x2 = e4.z + p4.z, x3 = e4.w + p4.w;
    float s  = blkSum128(x0 + x1 + x2 + x3, red);
    float sq = blkSum128(x0*x0 + x1*x1 + x2*x2 + x3*x3, red);
    float mean = s * (1.0f / D_);
    float var  = sq * (1.0f / D_) - mean * mean;
    float rstd = rsqrtf(var + 1e-5f);
    float4 g4 = ((const float4*)g)[tid], b4 = ((const float4*)b)[tid];
    float4 y;
    y.x = (x0 - mean) * rstd * g4.x + b4.x;
    y.y = (x1 - mean) * rstd * g4.y + b4.y;
    y.z = (x2 - mean) * rstd * g4.z + b4.z;
    y.w = (x3 - mean) * rstd * g4.w + b4.w;
    val4[(size_t)n * 128 + tid] = y;
    float4 w4 = ((const float4*)sw)[tid];
    float dot = blkSum128(y.x*w4.x + y.y*w4.y + y.z*w4.z + y.w*w4.w, red);
    if (tid == 0) st[n] = dot + sb[0];
}

// -------------------- kernel: tf32 tensor-core GEMM --------------------
// C(MxN) = A(MxK) @ B(KxN); A,B row-major fp32 (converted to tf32 in smem).
// Block tile 64x64x32, 128 threads (4 warps, 2x2 warp grid, 32x32 warp tile).
// EPI 0: plain; 1: gelu(AB + bias); 2: AB + bias + Cres
#define GBM 64
#define GBN 64
#define GBK 32
#define ASP 36   // padded A row stride (k-dim 32 + 4)
#define BSP 72   // padded B row stride (n-dim 64 + 8)

template <int EPI>
__global__ __launch_bounds__(128) void mma_gemm_kernel(
        const float* __restrict__ A, const float* __restrict__ B,
        float* __restrict__ C, const float* __restrict__ bias,
        const float* __restrict__ Cres, int M, int Nn, int Kk) {
    __shared__ unsigned As[GBM * ASP];   // As[row][k]
    __shared__ unsigned Bs[GBK * BSP];   // Bs[k][n]

    int tid  = threadIdx.x;
    int lane = tid & 31;
    int wid  = tid >> 5;          // 0..3
    int wm   = wid & 1;           // warp row (2)
    int wn   = wid >> 1;          // warp col (2)
    int g    = lane >> 2;         // groupID 0..7
    int tig  = lane & 3;          // thread-in-group 0..3

    int bm = blockIdx.x * GBM;
    int bn = blockIdx.y * GBN;

    float acc[2][4][4];
    #pragma unroll
    for (int i = 0; i < 2; i++)
        #pragma unroll
        for (int j = 0; j < 4; j++)
            #pragma unroll
            for (int c = 0; c < 4; c++) acc[i][j][c] = 0.f;

    const int KT = Kk / GBK;
    for (int kt = 0; kt < KT; kt++) {
        int k0 = kt * GBK;
        // ---- load A tile: 64 rows x 32 k = 512 float4, 4 per thread ----
        #pragma unroll
        for (int i = 0; i < 4; i++) {
            int idx = tid + i * 128;
            int row = idx >> 3;          // 0..63
            int seg = idx & 7;           // 0..7 (k/4)
            float4 v = make_float4(0.f, 0.f, 0.f, 0.f);
            if (bm + row < M)
                v = *(const float4*)(A + (size_t)(bm + row) * Kk + k0 + seg * 4);
            uint4 u;
            u.x = f2tf32(v.x); u.y = f2tf32(v.y); u.z = f2tf32(v.z); u.w = f2tf32(v.w);
            *(uint4*)(&As[row * ASP + seg * 4]) = u;
        }
        // ---- load B tile: 32 k x 64 n = 512 float4, 4 per thread ----
        #pragma unroll
        for (int i = 0; i < 4; i++) {
            int idx = tid + i * 128;
            int kr   = idx >> 4;          // 0..31
            int cseg = idx & 15;          // 0..15 (n/4)
            float4 v = *(const float4*)(B + (size_t)(k0 + kr) * Nn + bn + cseg * 4);
            uint4 u;
            u.x = f2tf32(v.x); u.y = f2tf32(v.y); u.z = f2tf32(v.z); u.w = f2tf32(v.w);
            *(uint4*)(&Bs[kr * BSP + cseg * 4]) = u;
        }
        __syncthreads();

        #pragma unroll
        for (int q = 0; q < 4; q++) {
            int kb = q * 8;
            unsigned af[2][4];
            #pragma unroll
            for (int mi = 0; mi < 2; mi++) {
                int rb = wm * 32 + mi * 16;
                af[mi][0] = As[(rb + g)     * ASP + kb + tig];
                af[mi][1] = As[(rb + g + 8) * ASP + kb + tig];
                af[mi][2] = As[(rb + g)     * ASP + kb + tig + 4];
                af[mi][3] = As[(rb + g + 8) * ASP + kb + tig + 4];
            }
            #pragma unroll
            for (int ni = 0; ni < 4; ni++) {
                int cb = wn * 32 + ni * 8 + g;
                unsigned b0 = Bs[(kb + tig)     * BSP + cb];
                unsigned b1 = Bs[(kb + tig + 4) * BSP + cb];
                mma_tf32(acc[0][ni], af[0], b0, b1);
                mma_tf32(acc[1][ni], af[1], b0, b1);
            }
        }
        __syncthreads();
    }

    // ---- epilogue ----
    #pragma unroll
    for (int mi = 0; mi < 2; mi++) {
        int row0 = bm + wm * 32 + mi * 16 + g;
        #pragma unroll
        for (int ni = 0; ni < 4; ni++) {
            int col = bn + wn * 32 + ni * 8 + tig * 2;
            float bx = 0.f, by = 0.f;
            if (EPI != 0) { bx = bias[col]; by = bias[col + 1]; }
            // rows row0 and row0+8
            #pragma unroll
            for (int rr = 0; rr < 2; rr++) {
                int row = row0 + rr * 8;
                if (row >= M) continue;
                float o0 = acc[mi][ni][rr * 2 + 0];
                float o1 = acc[mi][ni][rr * 2 + 1];
                if (EPI == 1) {
                    o0 = gelu_exact(o0 + bx);
                    o1 = gelu_exact(o1 + by);
                } else if (EPI == 2) {
                    const float2 r2 = *(const float2*)(Cres + (size_t)row * Nn + col);
                    o0 += bx + r2.x;
                    o1 += by + r2.y;
                }
                float2 o2 = make_float2(o0, o1);
                *(float2*)(C + (size_t)row * Nn + col) = o2;
            }
        }
    }
}

// -------------------- kernel: attention + residual + LN + LN2 (fused) --------------------
__global__ void attn_kernel(const float* __restrict__ val, const float* __restrict__ st_in,
                            const float* __restrict__ qk, float* __restrict__ val_out,
                            float* __restrict__ x_out, float* __restrict__ st_out,
                            const float* __restrict__ gate_arr, int l,
                            const float* __restrict__ lng, const float* __restrict__ lnb,
                            const float* __restrict__ ln2g, const float* __restrict__ ln2b) {
    __shared__ float s_q[128];
    __shared__ float s_a[K_];
    __shared__ int   s_j[K_];    // -1 encodes invalid
    __shared__ float s_e[K_];
    __shared__ float red[4];

    int n = blockIdx.x;
    int tid = threadIdx.x;
    int lane = tid & 31, wid = tid >> 5;
    float gate = gate_arr[l];

    s_q[tid] = qk[(size_t)n * 256 + tid];
    __syncthreads();

    const float scale = 0.17677669529663687f; // 1/sqrt(32)

    // ---- phase 1: per-neighbor head scores, head softmax, aggregate a ----
    for (int kk = wid; kk < K_; kk += 4) {
        int j; bool valid;
        if (kk == 0) { j = 0; valid = (n > W_); }
        else { int raw = n - (W_ + 1) + kk; valid = (raw >= 0); j = raw > 0 ? raw : 0; }
        const float* krow = qk + (size_t)j * 256 + 128;
        float p0 = s_q[lane]      * __ldg(krow + lane);
        float p1 = s_q[32 + lane] * __ldg(krow + 32 + lane);
        float p2 = s_q[64 + lane] * __ldg(krow + 64 + lane);
        float p3 = s_q[96 + lane] * __ldg(krow + 96 + lane);
        #pragma unroll
        for (int o = 16; o > 0; o >>= 1) {
            p0 += __shfl_xor_sync(0xffffffffu, p0, o);
            p1 += __shfl_xor_sync(0xffffffffu, p1, o);
            p2 += __shfl_xor_sync(0xffffffffu, p2, o);
            p3 += __shfl_xor_sync(0xffffffffu, p3, o);
        }
        if (lane == 0) {
            float s0 = p0 * scale, s1 = p1 * scale, s2 = p2 * scale, s3 = p3 * scale;
            float a0 = fabsf(s0), a1 = fabsf(s1), a2 = fabsf(s2), a3 = fabsf(s3);
            float m = fmaxf(fmaxf(a0, a1), fmaxf(a2, a3));
            float e0 = __expf(a0 - m), e1 = __expf(a1 - m), e2 = __expf(a2 - m), e3 = __expf(a3 - m);
            float den = e0 + e1 + e2 + e3;
            s_a[kk] = (s0 * e0 + s1 * e1 + s2 * e2 + s3 * e3) / den;
            s_j[kk] = valid ? j : -1;
        }
    }
    __syncthreads();

    // ---- phase 2: signed softmax over neighbors, times gathered state ----
    float a0v = s_a[tid]; int j0 = s_j[tid];
    float ab0 = (j0 >= 0) ? fabsf(a0v) : -1e30f;
    float a1v = 0.f; int j1 = -1; float ab1 = -1e30f;
    if (tid < K_ - 128) { a1v = s_a[128 + tid]; j1 = s_j[128 + tid]; ab1 = (j1 >= 0) ? fabsf(a1v) : -1e30f; }
    float mx = blkMax128(fmaxf(ab0, ab1), red);
    float e0 = (j0 >= 0) ? __expf(ab0 - mx) : 0.f;
    float e1 = (j1 >= 0) ? __expf(ab1 - mx) : 0.f;
    float inv = 1.0f / blkSum128(e0 + e1, red);

    float ds = 0.f;
    {
        float sg0 = (a0v > 0.f) ? 1.f : ((a0v < 0.f) ? -1.f : 0.f);
        float ee0 = (j0 >= 0) ? e0 * inv * sg0 * __ldg(st_in + j0) : 0.f;
        s_e[tid] = ee0; ds += ee0;
        if (tid < K_ - 128) {
            float sg1 = (a1v > 0.f) ? 1.f : ((a1v < 0.f) ? -1.f : 0.f);
            float ee1 = (j1 >= 0) ? e1 * inv * sg1 * __ldg(st_in + j1) : 0.f;
            s_e[128 + tid] = ee1; ds += ee1;
        }
    }
    float d_state = blkSum128(ds, red);  // internal syncthreads also publishes s_e

    // ---- phase 3: d_val gather, residual, LN, LN2 ----
    const float4* val4 = (const float4*)val;
    float4 acc = make_float4(0.f, 0.f, 0.f, 0.f);
    for (int kk = 0; kk < K_; kk++) {
        float e = s_e[kk];
        if (e != 0.f) {
            int j = s_j[kk];
            float4 v = __ldg(&val4[(size_t)j * 128 + tid]);
            acc.x = fmaf(e, v.x, acc.x);
            acc.y = fmaf(e, v.y, acc.y);
            acc.z = fmaf(e, v.z, acc.z);
            acc.w = fmaf(e, v.w, acc.w);
        }
    }
    float4 cur = val4[(size_t)n * 128 + tid];
    float x0 = cur.x + gate * acc.x;
    float x1 = cur.y + gate * acc.y;
    float x2 = cur.z + gate * acc.z;
    float x3 = cur.w + gate * acc.w;

    float s  = blkSum128(x0 + x1 + x2 + x3, red);
    float sq = blkSum128(x0*x0 + x1*x1 + x2*x2 + x3*x3, red);
    float mean = s * (1.0f / D_);
    float var  = sq * (1.0f / D_) - mean * mean;
    float rstd = rsqrtf(var + 1e-5f);
    float4 g4 = ((const float4*)lng)[tid], b4 = ((const float4*)lnb)[tid];
    float y0 = (x0 - mean) * rstd * g4.x + b4.x;
    float y1 = (x1 - mean) * rstd * g4.y + b4.y;
    float y2 = (x2 - mean) * rstd * g4.z + b4.z;
    float y3 = (x3 - mean) * rstd * g4.w + b4.w;
    ((float4*)val_out)[(size_t)n * 128 + tid] = make_float4(y0, y1, y2, y3);

    // second LN (ln2) fused -> FFN input
    float s2  = blkSum128(y0 + y1 + y2 + y3, red);
    float sq2 = blkSum128(y0*y0 + y1*y1 + y2*y2 + y3*y3, red);
    float mean2 = s2 * (1.0f / D_);
    float var2  = sq2 * (1.0f / D_) - mean2 * mean2;
    float rstd2 = rsqrtf(var2 + 1e-5f);
    float4 g24 = ((const float4*)ln2g)[tid], b24 = ((const float4*)ln2b)[tid];
    float4 xo;
    xo.x = (y0 - mean2) * rstd2 * g24.x + b24.x;
    xo.y = (y1 - mean2) * rstd2 * g24.y + b24.y;
    xo.z = (y2 - mean2) * rstd2 * g24.z + b24.z;
    xo.w = (y3 - mean2) * rstd2 * g24.w + b24.w;
    ((float4*)x_out)[(size_t)n * 128 + tid] = xo;

    if (tid == 0) st_out[n] = st_in[n] + gate * d_state;
}

// -------------------- launch --------------------
extern "C" void kernel_launch(void* const* d_in, const int* in_sizes, int n_in,
                              void* d_out, int out_size) {
    const int*   ids     = (const int*)d_in[0];
    const float* embed   = (const float*)d_in[1];
    const float* pos     = (const float*)d_in[2];
    const float* ln_in_g = (const float*)d_in[3];
    const float* ln_in_b = (const float*)d_in[4];
    const float* anc_st  = (const float*)d_in[5];
    const float* anc_val = (const float*)d_in[6];
    const float* state_w = (const float*)d_in[7];
    const float* state_b = (const float*)d_in[8];
    const float* wq      = (const float*)d_in[9];
    const float* wk      = (const float*)d_in[10];
    const float* gate    = (const float*)d_in[11];
    const float* ln_g    = (const float*)d_in[12];
    const float* ln_b    = (const float*)d_in[13];
    const float* ffn_w1  = (const float*)d_in[14];
    const float* ffn_b1  = (const float*)d_in[15];
    const float* ffn_w2  = (const float*)d_in[16];
    const float* ffn_b2  = (const float*)d_in[17];
    const float* ln2_g   = (const float*)d_in[18];
    const float* ln2_b   = (const float*)d_in[19];
    float* out = (float*)d_out;

    float *valA, *valB, *x, *h, *qk, *stA, *stB, *wqk;
    cudaGetSymbolAddress((void**)&valA, g_valA);
    cudaGetSymbolAddress((void**)&valB, g_valB);
    cudaGetSymbolAddress((void**)&x,    g_x);
    cudaGetSymbolAddress((void**)&h,    g_h);
    cudaGetSymbolAddress((void**)&qk,   g_qk);
    cudaGetSymbolAddress((void**)&stA,  g_stA);
    cudaGetSymbolAddress((void**)&stB,  g_stB);
    cudaGetSymbolAddress((void**)&wqk,  g_wqk);

    prep_wqk_kernel<<<(L_ * D_ * 256) / 256, 256>>>(wq, wk, wqk);
    embed_ln_kernel<<<N_, 128>>>(ids, embed, pos, ln_in_g, ln_in_b, anc_val, anc_st,
                                 state_w, state_b, valA, stA);

    float* s_in = stA;
    float* s_out = stB;
    const int MB = (N_ + GBM - 1) / GBM;   // 25
    for (int l = 0; l < L_; l++) {
        dim3 gqk(MB, 256 / GBN);
        mma_gemm_kernel<0><<<gqk, 128>>>(valA, wqk + (size_t)l * D_ * 256, qk,
                                         nullptr, nullptr, N_, 256, D_);
        attn_kernel<<<N_, 128>>>(valA, s_in, qk, valB, x, s_out, gate, l,
                                 ln_g + l * D_, ln_b + l * D_,
                                 ln2_g + l * D_, ln2_b + l * D_);
        dim3 g1(MB, HFF_ / GBN);
        mma_gemm_kernel<1><<<g1, 128>>>(x, ffn_w1 + (size_t)l * D_ * HFF_, h,
                                        ffn_b1 + l * HFF_, nullptr, N_, HFF_, D_);
        float* dst = (l == L_ - 1) ? out : valA;
        dim3 g2(MB, D_ / GBN);
        mma_gemm_kernel<2><<<g2, 128>>>(h, ffn_w2 + (size_t)l * HFF_ * D_, dst,
                                        ffn_b2 + l * D_, valB, N_, D_, HFF_);
        float* t = s_in; s_in = s_out; s_out = t;
    }
}